// round 2
// baseline (speedup 1.0000x reference)
#include <cuda_runtime.h>
#include <cuda_bf16.h>
#include <math.h>
#include <float.h>

#define T_TOT   16384
#define IN_DIM  3072
#define V_DIM   768
#define HEADS   4
#define KNN     32
#define N_KEYS  128
#define HALF    128
#define QDIM    (HEADS * 2 * HALF)   // 1024

// ---------------- scratch (device globals; no allocation allowed) ----------
__device__ float g_dense[(size_t)T_TOT * V_DIM];
__device__ float g_q[(size_t)T_TOT * QDIM];
__device__ float g_w[(size_t)T_TOT * HEADS * KNN];
__device__ int   g_i[(size_t)T_TOT * HEADS * KNN];

// ---------------- SGEMM: C[M,N] = A[M,K] * B[K,N] + bias ------------------
// BM=BN=128, BK=8, 256 threads, 8x8 per thread as 2x2 of 4x4 sub-tiles.
__global__ __launch_bounds__(256) void sgemm128(
    const float* __restrict__ A, const float* __restrict__ B,
    const float* __restrict__ bias, float* __restrict__ C,
    int N, int K)
{
    __shared__ float As[8][128];
    __shared__ float Bs[8][128];

    const int tid = threadIdx.x;
    const int bm = blockIdx.y, bn = blockIdx.x;
    const int tx = tid & 15;        // 0..15 -> cols tx*4 and tx*4+64
    const int ty = tid >> 4;        // 0..15 -> rows ty*4 and ty*4+64

    const int arow = tid >> 1;            // 0..127
    const int acol = (tid & 1) * 4;       // 0 or 4
    const int brow = tid >> 5;            // 0..7
    const int bcol = (tid & 31) * 4;      // 0..124

    const float* Aptr = A + (size_t)(bm * 128 + arow) * K + acol;
    const float* Bptr = B + (size_t)brow * N + bn * 128 + bcol;

    float acc[2][2][4][4];
#pragma unroll
    for (int a = 0; a < 2; a++)
#pragma unroll
        for (int b = 0; b < 2; b++)
#pragma unroll
            for (int i = 0; i < 4; i++)
#pragma unroll
                for (int j = 0; j < 4; j++) acc[a][b][i][j] = 0.f;

    for (int k0 = 0; k0 < K; k0 += 8) {
        float4 a4 = *(const float4*)Aptr;  Aptr += 8;
        float4 b4 = *(const float4*)Bptr;  Bptr += (size_t)8 * N;
        As[acol + 0][arow] = a4.x;
        As[acol + 1][arow] = a4.y;
        As[acol + 2][arow] = a4.z;
        As[acol + 3][arow] = a4.w;
        *(float4*)&Bs[brow][bcol] = b4;
        __syncthreads();

#pragma unroll
        for (int kk = 0; kk < 8; kk++) {
            float ar[2][4], br[2][4];
            *(float4*)ar[0] = *(const float4*)&As[kk][ty * 4];
            *(float4*)ar[1] = *(const float4*)&As[kk][ty * 4 + 64];
            *(float4*)br[0] = *(const float4*)&Bs[kk][tx * 4];
            *(float4*)br[1] = *(const float4*)&Bs[kk][tx * 4 + 64];
#pragma unroll
            for (int a = 0; a < 2; a++)
#pragma unroll
                for (int i = 0; i < 4; i++)
#pragma unroll
                    for (int b = 0; b < 2; b++)
#pragma unroll
                        for (int j = 0; j < 4; j++)
                            acc[a][b][i][j] += ar[a][i] * br[b][j];
        }
        __syncthreads();
    }

#pragma unroll
    for (int a = 0; a < 2; a++) {
#pragma unroll
        for (int i = 0; i < 4; i++) {
            int row = bm * 128 + ty * 4 + a * 64 + i;
            float* Crow = C + (size_t)row * N + bn * 128;
#pragma unroll
            for (int b = 0; b < 2; b++) {
                int c = tx * 4 + b * 64;
                float4 v;
                v.x = acc[a][b][i][0] + bias[bn * 128 + c + 0];
                v.y = acc[a][b][i][1] + bias[bn * 128 + c + 1];
                v.z = acc[a][b][i][2] + bias[bn * 128 + c + 2];
                v.w = acc[a][b][i][3] + bias[bn * 128 + c + 3];
                *(float4*)(Crow + c) = v;
            }
        }
    }
}

// ---------------- bitonic sort (ascending by value), 128 elems, 128 thr ----
__device__ __forceinline__ void bitonic128(float* s, int* si, int tid)
{
    for (int k = 2; k <= 128; k <<= 1) {
        for (int j = k >> 1; j > 0; j >>= 1) {
            int ixj = tid ^ j;
            if (ixj > tid) {
                bool up = ((tid & k) == 0);
                float a = s[tid], b = s[ixj];
                if ((a > b) == up) {
                    s[tid] = b; s[ixj] = a;
                    int t2 = si[tid]; si[tid] = si[ixj]; si[ixj] = t2;
                }
            }
            __syncthreads();
        }
    }
}

// ---------------- PKM scoring + top-k + softmax ----------------------------
// grid (T_TOT, HEADS), 128 threads; one block per (token, head)
__global__ __launch_bounds__(128) void pkm_topk(
    const float* __restrict__ Q, const float* __restrict__ keys,
    float* __restrict__ Wout, int* __restrict__ Iout)
{
    const int t = blockIdx.x, h = blockIdx.y;
    const int tid = threadIdx.x;

    __shared__ float q[2 * HALF];
    __shared__ float s[128];  __shared__ int si[128];
    __shared__ float v1[KNN]; __shared__ int i1[KNN];
    __shared__ float v2[KNN]; __shared__ int i2[KNN];
    __shared__ float cs[128]; __shared__ int ci[128];

    // load q for this (t,h): 256 floats
    q[tid]       = Q[(size_t)t * QDIM + h * 256 + tid];
    q[tid + 128] = Q[(size_t)t * QDIM + h * 256 + 128 + tid];
    __syncthreads();

    for (int side = 0; side < 2; side++) {
        // score: thread tid computes s[tid] = dot(q_side, keys[h,side,tid,:])
        const float4* K4 = (const float4*)(keys + (size_t)((h * 2 + side) * N_KEYS + tid) * HALF);
        const float4* q4 = (const float4*)(q + side * HALF);
        float acc = 0.f;
#pragma unroll
        for (int d = 0; d < HALF / 4; d++) {
            float4 kv = K4[d]; float4 qv = q4[d];
            acc += kv.x * qv.x + kv.y * qv.y + kv.z * qv.z + kv.w * qv.w;
        }
        s[tid] = acc; si[tid] = tid;
        __syncthreads();
        bitonic128(s, si, tid);
        if (tid < KNN) {
            // descending top-32
            if (side == 0) { v1[tid] = s[127 - tid]; i1[tid] = si[127 - tid]; }
            else           { v2[tid] = s[127 - tid]; i2[tid] = si[127 - tid]; }
        }
        __syncthreads();
    }

    // Pruned cartesian candidates: (i+1)*(j+1) <= 32 -> 119 candidates.
    if (tid < 119) {
        int r = tid, i = 0, c;
        while (r >= (c = 32 / (i + 1))) { r -= c; i++; }
        int j = r;
        cs[tid] = v1[i] + v2[j];
        ci[tid] = i1[i] * N_KEYS + i2[j];
    } else {
        cs[tid] = -FLT_MAX; ci[tid] = 0;
    }
    __syncthreads();
    bitonic128(cs, ci, tid);

    // top-32 at positions 127..96 (ascending sort); softmax within warp 0
    if (tid < KNN) {
        float b = cs[127 - tid];
        float mx = cs[127];
        float e = expf(b - mx);
        float sum = e;
#pragma unroll
        for (int o = 16; o > 0; o >>= 1) sum += __shfl_xor_sync(0xffffffffu, sum, o);
        size_t base = (size_t)t * (HEADS * KNN) + h * KNN + tid;
        Wout[base] = e / sum;
        Iout[base] = ci[127 - tid];
    }
}

// ---------------- gather + residual + LayerNorm ----------------------------
// one block per token; 192 threads, each owns one float4 (768 = 192*4)
__global__ __launch_bounds__(192) void pkm_out(
    const float* __restrict__ dense, const float* __restrict__ inp,
    const float* __restrict__ Wt, const int* __restrict__ It,
    const float* __restrict__ values, const float* __restrict__ gamma,
    const float* __restrict__ beta, float* __restrict__ out)
{
    const int t = blockIdx.x;
    const int tid = threadIdx.x;

    __shared__ float wsh[HEADS * KNN];
    __shared__ int   ish[HEADS * KNN];
    __shared__ float red[192];

    if (tid < HEADS * KNN) {
        wsh[tid] = Wt[(size_t)t * (HEADS * KNN) + tid];
        ish[tid] = It[(size_t)t * (HEADS * KNN) + tid];
    }
    __syncthreads();

    float4 acc;
    {
        float4 d4 = ((const float4*)(dense + (size_t)t * V_DIM))[tid];
        float4 r4 = ((const float4*)(inp   + (size_t)t * V_DIM))[tid];
        acc.x = d4.x + r4.x; acc.y = d4.y + r4.y;
        acc.z = d4.z + r4.z; acc.w = d4.w + r4.w;
    }

    // gather 128 value rows (dual accumulators for a bit of ILP)
    float4 acc2 = make_float4(0.f, 0.f, 0.f, 0.f);
#pragma unroll 4
    for (int m = 0; m < HEADS * KNN; m += 2) {
        float w0 = wsh[m];
        float4 v0 = ((const float4*)(values + (size_t)ish[m] * V_DIM))[tid];
        acc.x += w0 * v0.x; acc.y += w0 * v0.y; acc.z += w0 * v0.z; acc.w += w0 * v0.w;
        float w1 = wsh[m + 1];
        float4 v1 = ((const float4*)(values + (size_t)ish[m + 1] * V_DIM))[tid];
        acc2.x += w1 * v1.x; acc2.y += w1 * v1.y; acc2.z += w1 * v1.z; acc2.w += w1 * v1.w;
    }
    acc.x += acc2.x; acc.y += acc2.y; acc.z += acc2.z; acc.w += acc2.w;

    // ---- LayerNorm (two-pass) ----
    red[tid] = acc.x + acc.y + acc.z + acc.w;
    __syncthreads();
    if (tid < 64) red[tid] += red[tid + 128];
    __syncthreads();
    if (tid < 64) red[tid] += red[tid + 64];
    __syncthreads();
    if (tid < 32) {
        float v = red[tid] + red[tid + 32];
#pragma unroll
        for (int o = 16; o > 0; o >>= 1) v += __shfl_xor_sync(0xffffffffu, v, o);
        if (tid == 0) red[0] = v;
    }
    __syncthreads();
    float mu = red[0] * (1.0f / V_DIM);
    __syncthreads();

    float dx = acc.x - mu, dy = acc.y - mu, dz = acc.z - mu, dw = acc.w - mu;
    red[tid] = dx * dx + dy * dy + dz * dz + dw * dw;
    __syncthreads();
    if (tid < 64) red[tid] += red[tid + 128];
    __syncthreads();
    if (tid < 64) red[tid] += red[tid + 64];
    __syncthreads();
    if (tid < 32) {
        float v = red[tid] + red[tid + 32];
#pragma unroll
        for (int o = 16; o > 0; o >>= 1) v += __shfl_xor_sync(0xffffffffu, v, o);
        if (tid == 0) red[0] = v;
    }
    __syncthreads();
    float var = red[0] * (1.0f / V_DIM);
    float rstd = rsqrtf(var + 1e-12f);

    float4 g4 = ((const float4*)gamma)[tid];
    float4 b4 = ((const float4*)beta)[tid];
    float4 o4;
    o4.x = dx * rstd * g4.x + b4.x;
    o4.y = dy * rstd * g4.y + b4.y;
    o4.z = dz * rstd * g4.z + b4.z;
    o4.w = dw * rstd * g4.w + b4.w;
    ((float4*)(out + (size_t)t * V_DIM))[tid] = o4;
}

// ---------------- launch ---------------------------------------------------
extern "C" void kernel_launch(void* const* d_in, const int* in_sizes, int n_in,
                              void* d_out, int out_size)
{
    const float* hs     = (const float*)d_in[0];  // (T, 3072)
    const float* inp    = (const float*)d_in[1];  // (T, 768)
    const float* Wd     = (const float*)d_in[2];  // (3072, 768)
    const float* bd     = (const float*)d_in[3];  // (768)
    const float* Wq     = (const float*)d_in[4];  // (3072, 1024)
    const float* bq     = (const float*)d_in[5];  // (1024)
    const float* keys   = (const float*)d_in[6];  // (4,2,128,128)
    const float* values = (const float*)d_in[7];  // (16384, 768)
    const float* gamma  = (const float*)d_in[8];  // (768)
    const float* beta   = (const float*)d_in[9];  // (768)
    float* out = (float*)d_out;

    void *p_dense, *p_q, *p_w, *p_i;
    cudaGetSymbolAddress(&p_dense, g_dense);
    cudaGetSymbolAddress(&p_q, g_q);
    cudaGetSymbolAddress(&p_w, g_w);
    cudaGetSymbolAddress(&p_i, g_i);
    float* dense = (float*)p_dense;
    float* q     = (float*)p_q;
    float* wbuf  = (float*)p_w;
    int*   ibuf  = (int*)p_i;

    sgemm128<<<dim3(V_DIM / 128, T_TOT / 128), 256>>>(hs, Wd, bd, dense, V_DIM, IN_DIM);
    sgemm128<<<dim3(QDIM / 128, T_TOT / 128), 256>>>(hs, Wq, bq, q, QDIM, IN_DIM);
    pkm_topk<<<dim3(T_TOT, HEADS), 128>>>(q, keys, wbuf, ibuf);
    pkm_out<<<T_TOT, 192>>>(dense, inp, wbuf, ibuf, values, gamma, beta, out);
}

// round 5
// speedup vs baseline: 1.5288x; 1.5288x over previous
#include <cuda_runtime.h>
#include <cuda_bf16.h>
#include <math.h>
#include <float.h>
#include <stdint.h>

#define T_TOT   16384
#define IN_DIM  3072
#define V_DIM   768
#define HEADS   4
#define KNN     32
#define N_KEYS  128
#define HALF    128
#define NCAT    1792            // 768 (dense) + 1024 (q)
#define BM      128
#define BN      128
#define BK      64
#define STAGES  4
#define NCHUNK  144             // 3 * 3072 / 64
#define STAGE_BYTES (BM * BK * 2 + BN * BK * 2)   // 32768
#define SMEM_TOTAL  (STAGES * STAGE_BYTES)        // 131072

// ---------------- scratch (device globals; no allocation allowed) ----------
__device__ __align__(256) __nv_bfloat16 g_Ahi[(size_t)T_TOT * IN_DIM];
__device__ __align__(256) __nv_bfloat16 g_Alo[(size_t)T_TOT * IN_DIM];
__device__ __align__(256) __nv_bfloat16 g_Bhi[(size_t)NCAT * IN_DIM];
__device__ __align__(256) __nv_bfloat16 g_Blo[(size_t)NCAT * IN_DIM];
__device__ __align__(256) float g_bias[NCAT];
__device__ __align__(256) float g_C[(size_t)T_TOT * NCAT];
__device__ __align__(256) float g_w[(size_t)T_TOT * HEADS * KNN];
__device__ __align__(256) int   g_i[(size_t)T_TOT * HEADS * KNN];

// ---------------- PTX helpers ----------------------------------------------
__device__ __forceinline__ uint32_t smem_u32(const void* p) {
    uint32_t a;
    asm("{ .reg .u64 t; cvta.to.shared.u64 t, %1; cvt.u32.u64 %0, t; }" : "=r"(a) : "l"(p));
    return a;
}
#define SW128(off) ((off) ^ (((off) >> 3) & 0x70))

__device__ __forceinline__ void cp_async16(uint32_t dst, const void* src) {
    asm volatile("cp.async.cg.shared.global [%0], [%1], 16;" :: "r"(dst), "l"(src));
}
#define CP_COMMIT() asm volatile("cp.async.commit_group;" ::: "memory")
#define CP_WAIT2()  asm volatile("cp.async.wait_group 2;" ::: "memory")

#define LDSM4(r0, r1, r2, r3, addr) \
    asm volatile("ldmatrix.sync.aligned.m8n8.x4.shared.b16 {%0,%1,%2,%3}, [%4];" \
                 : "=r"(r0), "=r"(r1), "=r"(r2), "=r"(r3) : "r"(addr))

#define MMA16816(d, a0, a1, a2, a3, b0, b1) \
    asm volatile("mma.sync.aligned.m16n8k16.row.col.f32.bf16.bf16.f32 " \
                 "{%0,%1,%2,%3}, {%4,%5,%6,%7}, {%8,%9}, {%0,%1,%2,%3};" \
                 : "+f"((d)[0]), "+f"((d)[1]), "+f"((d)[2]), "+f"((d)[3]) \
                 : "r"(a0), "r"(a1), "r"(a2), "r"(a3), "r"(b0), "r"(b1))

// ---------------- conversion kernels ---------------------------------------
__global__ __launch_bounds__(256) void split_a(const float* __restrict__ X)
{
    size_t i = (size_t)blockIdx.x * 256 + threadIdx.x;   // one float4
    float4 v = ((const float4*)X)[i];
    __nv_bfloat16 hx = __float2bfloat16(v.x), hy = __float2bfloat16(v.y);
    __nv_bfloat16 hz = __float2bfloat16(v.z), hw = __float2bfloat16(v.w);
    ushort4 h, l;
    h.x = __bfloat16_as_ushort(hx); h.y = __bfloat16_as_ushort(hy);
    h.z = __bfloat16_as_ushort(hz); h.w = __bfloat16_as_ushort(hw);
    l.x = __bfloat16_as_ushort(__float2bfloat16(v.x - __bfloat162float(hx)));
    l.y = __bfloat16_as_ushort(__float2bfloat16(v.y - __bfloat162float(hy)));
    l.z = __bfloat16_as_ushort(__float2bfloat16(v.z - __bfloat162float(hz)));
    l.w = __bfloat16_as_ushort(__float2bfloat16(v.w - __bfloat162float(hw)));
    ((ushort4*)g_Ahi)[i] = h;
    ((ushort4*)g_Alo)[i] = l;
}

// W (K x N, row-major) -> B (N x K, bf16 hi/lo), rows offset by rowOff
__global__ __launch_bounds__(256) void transpose_split(
    const float* __restrict__ W, int N, int rowOff)
{
    __shared__ float tile[32][33];
    int n0 = blockIdx.x * 32, k0 = blockIdx.y * 32;
    int tx = threadIdx.x, ty = threadIdx.y;   // 32 x 8
#pragma unroll
    for (int j = 0; j < 32; j += 8)
        tile[ty + j][tx] = W[(size_t)(k0 + ty + j) * N + n0 + tx];
    __syncthreads();
#pragma unroll
    for (int j = 0; j < 32; j += 8) {
        int n = n0 + ty + j, k = k0 + tx;
        float v = tile[tx][ty + j];
        __nv_bfloat16 h = __float2bfloat16(v);
        __nv_bfloat16 lo = __float2bfloat16(v - __bfloat162float(h));
        size_t o = (size_t)(rowOff + n) * IN_DIM + k;
        g_Bhi[o] = h;
        g_Blo[o] = lo;
    }
}

__global__ void bias_cat(const float* __restrict__ bd, const float* __restrict__ bq)
{
    int i = blockIdx.x * 256 + threadIdx.x;
    if (i < V_DIM) g_bias[i] = bd[i];
    else if (i < NCAT) g_bias[i] = bq[i - V_DIM];
}

// ---------------- HMMA GEMM: C = [A_hi|A_lo|A_hi] x [B_hi;B_hi;B_lo]^T -----
__device__ __forceinline__ void load_chunk(
    int chunk, int s, int tid, int bm, int bn, uint32_t sb)
{
    const __nv_bfloat16* Ab = (chunk < 48 || chunk >= 96) ? g_Ahi : g_Alo;
    const __nv_bfloat16* Bb = (chunk < 96) ? g_Bhi : g_Blo;
    int k0 = (chunk % 48) * BK;
    const __nv_bfloat16* Ag = Ab + (size_t)(bm * BM) * IN_DIM + k0;
    const __nv_bfloat16* Bg = Bb + (size_t)(bn * BN) * IN_DIM + k0;
    uint32_t sA = sb + s * STAGE_BYTES;
    uint32_t sB = sA + BM * BK * 2;
#pragma unroll
    for (int it = 0; it < 4; it++) {
        int u = tid + it * 256;               // 1024 chunks of 16B each side
        int r = u >> 3, ch = u & 7;
        cp_async16(sA + SW128(r * 128 + ch * 16), Ag + (size_t)r * IN_DIM + ch * 8);
        cp_async16(sB + SW128(r * 128 + ch * 16), Bg + (size_t)r * IN_DIM + ch * 8);
    }
}

__global__ __launch_bounds__(256, 1) void gemm_hmma(float* __restrict__ C)
{
    extern __shared__ char smem[];
    uint32_t sb = smem_u32(smem);
    const int tid = threadIdx.x, wid = tid >> 5, lane = tid & 31;
    const int bn = blockIdx.x, bm = blockIdx.y;
    const int wm = wid & 3;          // 0..3 -> m offset wm*32
    const int wn = wid >> 2;         // 0..1 -> n offset wn*64

    float acc[2][8][4];
#pragma unroll
    for (int a = 0; a < 2; a++)
#pragma unroll
        for (int b = 0; b < 8; b++)
#pragma unroll
            for (int c = 0; c < 4; c++) acc[a][b][c] = 0.f;

    // per-lane ldmatrix row/chunk bases
    const int sub = lane >> 3, lr = lane & 7;
    const int arow0 = wm * 32 + ((sub & 1) << 3) + lr;   // + mi*16
    const int akc = sub >> 1;                            // chunk offset in kstep
    const int brow0 = wn * 64 + ((sub >> 1) << 3) + lr;  // + nj*16
    const int bkc = sub & 1;

    // prologue: stages 0..2
#pragma unroll
    for (int s = 0; s < STAGES - 1; s++) {
        load_chunk(s, s, tid, bm, bn, sb);
        CP_COMMIT();
    }

    for (int i = 0; i < NCHUNK; i++) {
        const int s = i & (STAGES - 1);
        CP_WAIT2();
        __syncthreads();
        const int nc = i + STAGES - 1;
        if (nc < NCHUNK) load_chunk(nc, nc & (STAGES - 1), tid, bm, bn, sb);
        CP_COMMIT();

        const uint32_t sA = sb + s * STAGE_BYTES;
        const uint32_t sB = sA + BM * BK * 2;
#pragma unroll
        for (int ks = 0; ks < 4; ks++) {
            uint32_t a[2][4];
#pragma unroll
            for (int mi = 0; mi < 2; mi++) {
                int row = arow0 + mi * 16;
                uint32_t ad = sA + row * 128 + (((2 * ks + akc) ^ (row & 7)) << 4);
                LDSM4(a[mi][0], a[mi][1], a[mi][2], a[mi][3], ad);
            }
            uint32_t b[4][4];
#pragma unroll
            for (int nj = 0; nj < 4; nj++) {
                int row = brow0 + nj * 16;
                uint32_t bd = sB + row * 128 + (((2 * ks + bkc) ^ (row & 7)) << 4);
                LDSM4(b[nj][0], b[nj][1], b[nj][2], b[nj][3], bd);
            }
#pragma unroll
            for (int mi = 0; mi < 2; mi++)
#pragma unroll
                for (int nj = 0; nj < 4; nj++) {
                    MMA16816(acc[mi][2 * nj],     a[mi][0], a[mi][1], a[mi][2], a[mi][3],
                             b[nj][0], b[nj][1]);
                    MMA16816(acc[mi][2 * nj + 1], a[mi][0], a[mi][1], a[mi][2], a[mi][3],
                             b[nj][2], b[nj][3]);
                }
        }
    }

    // epilogue: direct STG with bias
    const int mrow = bm * BM + wm * 32 + (lane >> 2);
    const int ncol = bn * BN + wn * 64 + 2 * (lane & 3);
#pragma unroll
    for (int nj = 0; nj < 8; nj++) {
        int c = ncol + nj * 8;
        float b0 = g_bias[c], b1 = g_bias[c + 1];
#pragma unroll
        for (int mi = 0; mi < 2; mi++) {
            int r0 = mrow + mi * 16;
            float2 v0 = make_float2(acc[mi][nj][0] + b0, acc[mi][nj][1] + b1);
            float2 v1 = make_float2(acc[mi][nj][2] + b0, acc[mi][nj][3] + b1);
            *(float2*)(C + (size_t)r0 * NCAT + c) = v0;
            *(float2*)(C + (size_t)(r0 + 8) * NCAT + c) = v1;
        }
    }
}

// ---------------- bitonic sort (ascending by value), 128 elems, 128 thr ----
__device__ __forceinline__ void bitonic128(float* s, int* si, int tid)
{
    for (int k = 2; k <= 128; k <<= 1) {
        for (int j = k >> 1; j > 0; j >>= 1) {
            int ixj = tid ^ j;
            if (ixj > tid) {
                bool up = ((tid & k) == 0);
                float a = s[tid], b = s[ixj];
                if ((a > b) == up) {
                    s[tid] = b; s[ixj] = a;
                    int t2 = si[tid]; si[tid] = si[ixj]; si[ixj] = t2;
                }
            }
            __syncthreads();
        }
    }
}

// ---------------- PKM scoring + top-k + softmax ----------------------------
__global__ __launch_bounds__(128) void pkm_topk(
    const float* __restrict__ Cmat, const float* __restrict__ keys,
    float* __restrict__ Wout, int* __restrict__ Iout)
{
    const int t = blockIdx.x, h = blockIdx.y;
    const int tid = threadIdx.x;

    __shared__ float q[2 * HALF];
    __shared__ float s[128];  __shared__ int si[128];
    __shared__ float v1[KNN]; __shared__ int i1[KNN];
    __shared__ float v2[KNN]; __shared__ int i2[KNN];
    __shared__ float cs[128]; __shared__ int ci[128];

    const float* Qrow = Cmat + (size_t)t * NCAT + V_DIM + h * 256;
    q[tid]       = Qrow[tid];
    q[tid + 128] = Qrow[tid + 128];
    __syncthreads();

    for (int side = 0; side < 2; side++) {
        const float4* K4 = (const float4*)(keys + (size_t)((h * 2 + side) * N_KEYS + tid) * HALF);
        const float4* q4 = (const float4*)(q + side * HALF);
        float acc = 0.f;
#pragma unroll
        for (int d = 0; d < HALF / 4; d++) {
            float4 kv = K4[d]; float4 qv = q4[d];
            acc += kv.x * qv.x + kv.y * qv.y + kv.z * qv.z + kv.w * qv.w;
        }
        s[tid] = acc; si[tid] = tid;
        __syncthreads();
        bitonic128(s, si, tid);
        if (tid < KNN) {
            if (side == 0) { v1[tid] = s[127 - tid]; i1[tid] = si[127 - tid]; }
            else           { v2[tid] = s[127 - tid]; i2[tid] = si[127 - tid]; }
        }
        __syncthreads();
    }

    if (tid < 119) {
        int r = tid, i = 0, c;
        while (r >= (c = 32 / (i + 1))) { r -= c; i++; }
        int j = r;
        cs[tid] = v1[i] + v2[j];
        ci[tid] = i1[i] * N_KEYS + i2[j];
    } else {
        cs[tid] = -FLT_MAX; ci[tid] = 0;
    }
    __syncthreads();
    bitonic128(cs, ci, tid);

    if (tid < KNN) {
        float b = cs[127 - tid];
        float mx = cs[127];
        float e = expf(b - mx);
        float sum = e;
#pragma unroll
        for (int o = 16; o > 0; o >>= 1) sum += __shfl_xor_sync(0xffffffffu, sum, o);
        size_t base = (size_t)t * (HEADS * KNN) + h * KNN + tid;
        Wout[base] = e / sum;
        Iout[base] = ci[127 - tid];
    }
}

// ---------------- gather + residual + LayerNorm ----------------------------
__global__ __launch_bounds__(192) void pkm_out(
    const float* __restrict__ Cmat, const float* __restrict__ inp,
    const float* __restrict__ Wt, const int* __restrict__ It,
    const float* __restrict__ values, const float* __restrict__ gamma,
    const float* __restrict__ beta, float* __restrict__ out)
{
    const int t = blockIdx.x;
    const int tid = threadIdx.x;

    __shared__ float wsh[HEADS * KNN];
    __shared__ int   ish[HEADS * KNN];
    __shared__ float red[192];

    if (tid < HEADS * KNN) {
        wsh[tid] = Wt[(size_t)t * (HEADS * KNN) + tid];
        ish[tid] = It[(size_t)t * (HEADS * KNN) + tid];
    }
    __syncthreads();

    float4 acc;
    {
        float4 d4 = ((const float4*)(Cmat + (size_t)t * NCAT))[tid];
        float4 r4 = ((const float4*)(inp  + (size_t)t * V_DIM))[tid];
        acc.x = d4.x + r4.x; acc.y = d4.y + r4.y;
        acc.z = d4.z + r4.z; acc.w = d4.w + r4.w;
    }

    float4 acc2 = make_float4(0.f, 0.f, 0.f, 0.f);
#pragma unroll 4
    for (int m = 0; m < HEADS * KNN; m += 2) {
        float w0 = wsh[m];
        float4 v0 = ((const float4*)(values + (size_t)ish[m] * V_DIM))[tid];
        acc.x += w0 * v0.x; acc.y += w0 * v0.y; acc.z += w0 * v0.z; acc.w += w0 * v0.w;
        float w1 = wsh[m + 1];
        float4 v1 = ((const float4*)(values + (size_t)ish[m + 1] * V_DIM))[tid];
        acc2.x += w1 * v1.x; acc2.y += w1 * v1.y; acc2.z += w1 * v1.z; acc2.w += w1 * v1.w;
    }
    acc.x += acc2.x; acc.y += acc2.y; acc.z += acc2.z; acc.w += acc2.w;

    red[tid] = acc.x + acc.y + acc.z + acc.w;
    __syncthreads();
    if (tid < 64) red[tid] += red[tid + 128];
    __syncthreads();
    if (tid < 64) red[tid] += red[tid + 64];
    __syncthreads();
    if (tid < 32) {
        float v = red[tid] + red[tid + 32];
#pragma unroll
        for (int o = 16; o > 0; o >>= 1) v += __shfl_xor_sync(0xffffffffu, v, o);
        if (tid == 0) red[0] = v;
    }
    __syncthreads();
    float mu = red[0] * (1.0f / V_DIM);
    __syncthreads();

    float dx = acc.x - mu, dy = acc.y - mu, dz = acc.z - mu, dw = acc.w - mu;
    red[tid] = dx * dx + dy * dy + dz * dz + dw * dw;
    __syncthreads();
    if (tid < 64) red[tid] += red[tid + 128];
    __syncthreads();
    if (tid < 64) red[tid] += red[tid + 64];
    __syncthreads();
    if (tid < 32) {
        float v = red[tid] + red[tid + 32];
#pragma unroll
        for (int o = 16; o > 0; o >>= 1) v += __shfl_xor_sync(0xffffffffu, v, o);
        if (tid == 0) red[0] = v;
    }
    __syncthreads();
    float var = red[0] * (1.0f / V_DIM);
    float rstd = rsqrtf(var + 1e-12f);

    float4 g4 = ((const float4*)gamma)[tid];
    float4 b4 = ((const float4*)beta)[tid];
    float4 o4;
    o4.x = dx * rstd * g4.x + b4.x;
    o4.y = dy * rstd * g4.y + b4.y;
    o4.z = dz * rstd * g4.z + b4.z;
    o4.w = dw * rstd * g4.w + b4.w;
    ((float4*)(out + (size_t)t * V_DIM))[tid] = o4;
}

// ---------------- launch ---------------------------------------------------
extern "C" void kernel_launch(void* const* d_in, const int* in_sizes, int n_in,
                              void* d_out, int out_size)
{
    const float* hs     = (const float*)d_in[0];
    const float* inp    = (const float*)d_in[1];
    const float* Wd     = (const float*)d_in[2];
    const float* bd     = (const float*)d_in[3];
    const float* Wq     = (const float*)d_in[4];
    const float* bq     = (const float*)d_in[5];
    const float* keys   = (const float*)d_in[6];
    const float* values = (const float*)d_in[7];
    const float* gamma  = (const float*)d_in[8];
    const float* beta   = (const float*)d_in[9];
    float* out = (float*)d_out;

    void *p_C, *p_w, *p_i;
    cudaGetSymbolAddress(&p_C, g_C);
    cudaGetSymbolAddress(&p_w, g_w);
    cudaGetSymbolAddress(&p_i, g_i);
    float* C    = (float*)p_C;
    float* wbuf = (float*)p_w;
    int*   ibuf = (int*)p_i;

    cudaFuncSetAttribute(gemm_hmma, cudaFuncAttributeMaxDynamicSharedMemorySize, SMEM_TOTAL);

    split_a<<<(T_TOT * IN_DIM / 4) / 256, 256>>>(hs);
    transpose_split<<<dim3(V_DIM / 32, IN_DIM / 32), dim3(32, 8)>>>(Wd, V_DIM, 0);
    transpose_split<<<dim3(1024 / 32, IN_DIM / 32), dim3(32, 8)>>>(Wq, 1024, V_DIM);
    bias_cat<<<7, 256>>>(bd, bq);
    gemm_hmma<<<dim3(NCAT / BN, T_TOT / BM), 256, SMEM_TOTAL>>>(C);
    pkm_topk<<<dim3(T_TOT, HEADS), 128>>>(C, keys, wbuf, ibuf);
    pkm_out<<<T_TOT, 192>>>(C, inp, wbuf, ibuf, values, gamma, beta, out);
}

// round 6
// speedup vs baseline: 3.0252x; 1.9787x over previous
#include <cuda_runtime.h>
#include <cuda_fp16.h>
#include <math.h>
#include <float.h>
#include <stdint.h>

#define T_TOT   16384
#define IN_DIM  3072
#define V_DIM   768
#define HEADS   4
#define KNN     32
#define N_KEYS  128
#define HALF    128
#define NCAT    1792            // 768 (dense) + 1024 (scores)
#define BM      128
#define BN      128
#define BK      64
#define STAGES  4
#define NCHUNK  96              // 2 * 3072 / 64  (fp16 2-term split)
#define STAGE_BYTES (BM * BK * 2 + BN * BK * 2)   // 32768
#define SMEM_TOTAL  (STAGES * STAGE_BYTES)        // 131072
#define PREP_SMEM   (128 * 129 * 4 + 128 * 128 * 4)  // 131584

// ---------------- scratch (device globals; no allocation allowed) ----------
__device__ __align__(256) __half g_Ah[(size_t)T_TOT * IN_DIM];
__device__ __align__(256) __half g_Al[(size_t)T_TOT * IN_DIM];
__device__ __align__(256) __half g_Bh[(size_t)NCAT * IN_DIM];
__device__ __align__(256) float g_bias[NCAT];
__device__ __align__(256) float g_C[(size_t)T_TOT * NCAT];
__device__ __align__(256) float g_w[(size_t)T_TOT * HEADS * KNN];
__device__ __align__(256) int   g_i[(size_t)T_TOT * HEADS * KNN];

// ---------------- PTX helpers ----------------------------------------------
__device__ __forceinline__ uint32_t smem_u32(const void* p) {
    uint32_t a;
    asm("{ .reg .u64 t; cvta.to.shared.u64 t, %1; cvt.u32.u64 %0, t; }" : "=r"(a) : "l"(p));
    return a;
}
#define SW128(off) ((off) ^ (((off) >> 3) & 0x70))

__device__ __forceinline__ void cp_async16(uint32_t dst, const void* src) {
    asm volatile("cp.async.cg.shared.global [%0], [%1], 16;" :: "r"(dst), "l"(src));
}
#define CP_COMMIT() asm volatile("cp.async.commit_group;" ::: "memory")
#define CP_WAIT2()  asm volatile("cp.async.wait_group 2;" ::: "memory")

#define LDSM4(r0, r1, r2, r3, addr) \
    asm volatile("ldmatrix.sync.aligned.m8n8.x4.shared.b16 {%0,%1,%2,%3}, [%4];" \
                 : "=r"(r0), "=r"(r1), "=r"(r2), "=r"(r3) : "r"(addr))

#define MMA16816(d, a0, a1, a2, a3, b0, b1) \
    asm volatile("mma.sync.aligned.m16n8k16.row.col.f32.f16.f16.f32 " \
                 "{%0,%1,%2,%3}, {%4,%5,%6,%7}, {%8,%9}, {%0,%1,%2,%3};" \
                 : "+f"((d)[0]), "+f"((d)[1]), "+f"((d)[2]), "+f"((d)[3]) \
                 : "r"(a0), "r"(a1), "r"(a2), "r"(a3), "r"(b0), "r"(b1))

// ---------------- prep kernels ----------------------------------------------
// split hidden states into two fp16 terms (x = hi + lo, exact to ~2^-22)
__global__ __launch_bounds__(256) void split_a(const float* __restrict__ X)
{
    size_t i = (size_t)blockIdx.x * 256 + threadIdx.x;   // one float4
    float4 v = ((const float4*)X)[i];
    __half hx = __float2half_rn(v.x), hy = __float2half_rn(v.y);
    __half hz = __float2half_rn(v.z), hw = __float2half_rn(v.w);
    ushort4 h, l;
    h.x = __half_as_ushort(hx); h.y = __half_as_ushort(hy);
    h.z = __half_as_ushort(hz); h.w = __half_as_ushort(hw);
    l.x = __half_as_ushort(__float2half_rn(v.x - __half2float(hx)));
    l.y = __half_as_ushort(__float2half_rn(v.y - __half2float(hy)));
    l.z = __half_as_ushort(__float2half_rn(v.z - __half2float(hz)));
    l.w = __half_as_ushort(__float2half_rn(v.w - __half2float(hw)));
    ((ushort4*)g_Ah)[i] = h;
    ((ushort4*)g_Al)[i] = l;
}

// W_dense (3072 x 768 row-major) -> g_Bh rows 0..767 (N x K, fp16)
__global__ __launch_bounds__(256) void transpose_dense(const float* __restrict__ W)
{
    __shared__ float tile[32][33];
    int n0 = blockIdx.x * 32, k0 = blockIdx.y * 32;
    int tx = threadIdx.x, ty = threadIdx.y;   // 32 x 8
#pragma unroll
    for (int j = 0; j < 32; j += 8)
        tile[ty + j][tx] = W[(size_t)(k0 + ty + j) * V_DIM + n0 + tx];
    __syncthreads();
#pragma unroll
    for (int j = 0; j < 32; j += 8) {
        int n = n0 + ty + j, k = k0 + tx;
        g_Bh[(size_t)n * IN_DIM + k] = __float2half_rn(tile[tx][ty + j]);
    }
}

// merged: W_keff = Wq x keys^T (rows 768..1791 of g_Bh), score bias, dense bias
__global__ __launch_bounds__(256) void prep_misc(
    const float* __restrict__ Wq, const float* __restrict__ keys,
    const float* __restrict__ bd, const float* __restrict__ bq)
{
    extern __shared__ float sm[];
    float (*Ws)[129] = (float(*)[129])sm;                 // [kloc][d]
    float (*Ks)[128] = (float(*)[128])(sm + 128 * 129);   // [n][d]
    const int b = blockIdx.x, t = threadIdx.x;

    if (b < 192) {
        // W_keff[hs*128+n][kt*128+kloc] = sum_d Wq[k][hs*128+d] * keys[hs*128+n][d]
        const int hs = b & 7, kt = b >> 3;
        for (int i = t; i < 128 * 128; i += 256) {
            int r = i >> 7, d = i & 127;
            Ws[r][d] = Wq[(size_t)(kt * 128 + r) * 1024 + hs * 128 + d];
            Ks[r][d] = keys[(size_t)(hs * 128 + r) * 128 + d];
        }
        __syncthreads();
        const int kloc = t & 127, nh = t >> 7;
        for (int no = 0; no < 64; no++) {
            int n = nh * 64 + no;
            float acc = 0.f;
#pragma unroll 8
            for (int d = 0; d < 128; d++) acc += Ws[kloc][d] * Ks[n][d];
            g_Bh[(size_t)(V_DIM + hs * 128 + n) * IN_DIM + kt * 128 + kloc] =
                __float2half_rn(acc);
        }
    } else if (b < 196) {
        // score bias: sb[n'] = sum_d bq[hs*128+d] * keys[hs*128+n][d]
        int np = (b - 192) * 256 + t;     // 0..1023
        int hs = np >> 7, n = np & 127;
        float acc = 0.f;
        for (int d = 0; d < 128; d++)
            acc += bq[hs * 128 + d] * keys[(size_t)(hs * 128 + n) * 128 + d];
        g_bias[V_DIM + np] = acc;
    } else {
        for (int i = t; i < V_DIM; i += 256) g_bias[i] = bd[i];
    }
}

// ---------------- HMMA GEMM: C = [A_hi | A_lo] x [B; B]^T ------------------
__device__ __forceinline__ void load_chunk(
    int chunk, int s, int tid, int bm, int bn, uint32_t sb)
{
    const __half* Ab = (chunk < 48) ? g_Ah : g_Al;
    int k0 = (chunk < 48 ? chunk : chunk - 48) * BK;
    const __half* Ag = Ab + (size_t)(bm * BM) * IN_DIM + k0;
    const __half* Bg = g_Bh + (size_t)(bn * BN) * IN_DIM + k0;
    uint32_t sA = sb + s * STAGE_BYTES;
    uint32_t sB = sA + BM * BK * 2;
#pragma unroll
    for (int it = 0; it < 4; it++) {
        int u = tid + it * 256;               // 1024 chunks of 16B each side
        int r = u >> 3, ch = u & 7;
        cp_async16(sA + SW128(r * 128 + ch * 16), Ag + (size_t)r * IN_DIM + ch * 8);
        cp_async16(sB + SW128(r * 128 + ch * 16), Bg + (size_t)r * IN_DIM + ch * 8);
    }
}

__global__ __launch_bounds__(256, 1) void gemm_hmma(float* __restrict__ C)
{
    extern __shared__ char smem[];
    uint32_t sb = smem_u32(smem);
    const int tid = threadIdx.x, wid = tid >> 5, lane = tid & 31;
    const int bn = blockIdx.x, bm = blockIdx.y;
    const int wm = wid & 3;          // 0..3 -> m offset wm*32
    const int wn = wid >> 2;         // 0..1 -> n offset wn*64

    float acc[2][8][4];
#pragma unroll
    for (int a = 0; a < 2; a++)
#pragma unroll
        for (int b = 0; b < 8; b++)
#pragma unroll
            for (int c = 0; c < 4; c++) acc[a][b][c] = 0.f;

    const int sub = lane >> 3, lr = lane & 7;
    const int arow0 = wm * 32 + ((sub & 1) << 3) + lr;   // + mi*16
    const int akc = sub >> 1;
    const int brow0 = wn * 64 + ((sub >> 1) << 3) + lr;  // + nj*16
    const int bkc = sub & 1;

#pragma unroll
    for (int s = 0; s < STAGES - 1; s++) {
        load_chunk(s, s, tid, bm, bn, sb);
        CP_COMMIT();
    }

    for (int i = 0; i < NCHUNK; i++) {
        const int s = i & (STAGES - 1);
        CP_WAIT2();
        __syncthreads();
        const int nc = i + STAGES - 1;
        if (nc < NCHUNK) load_chunk(nc, nc & (STAGES - 1), tid, bm, bn, sb);
        CP_COMMIT();

        const uint32_t sA = sb + s * STAGE_BYTES;
        const uint32_t sB = sA + BM * BK * 2;
#pragma unroll
        for (int ks = 0; ks < 4; ks++) {
            uint32_t a[2][4];
#pragma unroll
            for (int mi = 0; mi < 2; mi++) {
                int row = arow0 + mi * 16;
                uint32_t ad = sA + row * 128 + (((2 * ks + akc) ^ (row & 7)) << 4);
                LDSM4(a[mi][0], a[mi][1], a[mi][2], a[mi][3], ad);
            }
            uint32_t b[4][4];
#pragma unroll
            for (int nj = 0; nj < 4; nj++) {
                int row = brow0 + nj * 16;
                uint32_t bd = sB + row * 128 + (((2 * ks + bkc) ^ (row & 7)) << 4);
                LDSM4(b[nj][0], b[nj][1], b[nj][2], b[nj][3], bd);
            }
#pragma unroll
            for (int mi = 0; mi < 2; mi++)
#pragma unroll
                for (int nj = 0; nj < 4; nj++) {
                    MMA16816(acc[mi][2 * nj],     a[mi][0], a[mi][1], a[mi][2], a[mi][3],
                             b[nj][0], b[nj][1]);
                    MMA16816(acc[mi][2 * nj + 1], a[mi][0], a[mi][1], a[mi][2], a[mi][3],
                             b[nj][2], b[nj][3]);
                }
        }
    }

    const int mrow = bm * BM + wm * 32 + (lane >> 2);
    const int ncol = bn * BN + wn * 64 + 2 * (lane & 3);
#pragma unroll
    for (int nj = 0; nj < 8; nj++) {
        int c = ncol + nj * 8;
        float b0 = g_bias[c], b1 = g_bias[c + 1];
#pragma unroll
        for (int mi = 0; mi < 2; mi++) {
            int r0 = mrow + mi * 16;
            float2 v0 = make_float2(acc[mi][nj][0] + b0, acc[mi][nj][1] + b1);
            float2 v1 = make_float2(acc[mi][nj][2] + b0, acc[mi][nj][3] + b1);
            *(float2*)(C + (size_t)r0 * NCAT + c) = v0;
            *(float2*)(C + (size_t)(r0 + 8) * NCAT + c) = v1;
        }
    }
}

// ---------------- bitonic sort (ascending by value), 128 elems, 128 thr ----
__device__ __forceinline__ void bitonic128(float* s, int* si, int tid)
{
    for (int k = 2; k <= 128; k <<= 1) {
        for (int j = k >> 1; j > 0; j >>= 1) {
            int ixj = tid ^ j;
            if (ixj > tid) {
                bool up = ((tid & k) == 0);
                float a = s[tid], b = s[ixj];
                if ((a > b) == up) {
                    s[tid] = b; s[ixj] = a;
                    int t2 = si[tid]; si[tid] = si[ixj]; si[ixj] = t2;
                }
            }
            __syncthreads();
        }
    }
}

// ---------------- PKM top-k + softmax (scores precomputed in C) ------------
__global__ __launch_bounds__(128) void pkm_topk(
    const float* __restrict__ Cmat,
    float* __restrict__ Wout, int* __restrict__ Iout)
{
    const int t = blockIdx.x, h = blockIdx.y;
    const int tid = threadIdx.x;

    __shared__ float s[128];  __shared__ int si[128];
    __shared__ float v1[KNN]; __shared__ int i1[KNN];
    __shared__ float v2[KNN]; __shared__ int i2[KNN];
    __shared__ float cs[128]; __shared__ int ci[128];

    const float* Srow = Cmat + (size_t)t * NCAT + V_DIM + h * 256;

    for (int side = 0; side < 2; side++) {
        s[tid] = Srow[side * 128 + tid]; si[tid] = tid;
        __syncthreads();
        bitonic128(s, si, tid);
        if (tid < KNN) {
            if (side == 0) { v1[tid] = s[127 - tid]; i1[tid] = si[127 - tid]; }
            else           { v2[tid] = s[127 - tid]; i2[tid] = si[127 - tid]; }
        }
        __syncthreads();
    }

    // pruned cartesian candidates: (i+1)*(j+1) <= 32 -> 119 candidates
    if (tid < 119) {
        int r = tid, i = 0, c;
        while (r >= (c = 32 / (i + 1))) { r -= c; i++; }
        int j = r;
        cs[tid] = v1[i] + v2[j];
        ci[tid] = i1[i] * N_KEYS + i2[j];
    } else {
        cs[tid] = -FLT_MAX; ci[tid] = 0;
    }
    __syncthreads();
    bitonic128(cs, ci, tid);

    if (tid < KNN) {
        float b = cs[127 - tid];
        float mx = cs[127];
        float e = expf(b - mx);
        float sum = e;
#pragma unroll
        for (int o = 16; o > 0; o >>= 1) sum += __shfl_xor_sync(0xffffffffu, sum, o);
        size_t base = (size_t)t * (HEADS * KNN) + h * KNN + tid;
        Wout[base] = e / sum;
        Iout[base] = ci[127 - tid];
    }
}

// ---------------- gather + residual + LayerNorm ----------------------------
__global__ __launch_bounds__(192) void pkm_out(
    const float* __restrict__ Cmat, const float* __restrict__ inp,
    const float* __restrict__ Wt, const int* __restrict__ It,
    const float* __restrict__ values, const float* __restrict__ gamma,
    const float* __restrict__ beta, float* __restrict__ out)
{
    const int t = blockIdx.x;
    const int tid = threadIdx.x;

    __shared__ float wsh[HEADS * KNN];
    __shared__ int   ish[HEADS * KNN];
    __shared__ float red[192];

    if (tid < HEADS * KNN) {
        wsh[tid] = Wt[(size_t)t * (HEADS * KNN) + tid];
        ish[tid] = It[(size_t)t * (HEADS * KNN) + tid];
    }
    __syncthreads();

    float4 acc;
    {
        float4 d4 = ((const float4*)(Cmat + (size_t)t * NCAT))[tid];
        float4 r4 = ((const float4*)(inp  + (size_t)t * V_DIM))[tid];
        acc.x = d4.x + r4.x; acc.y = d4.y + r4.y;
        acc.z = d4.z + r4.z; acc.w = d4.w + r4.w;
    }

    float4 acc2 = make_float4(0.f, 0.f, 0.f, 0.f);
#pragma unroll 4
    for (int m = 0; m < HEADS * KNN; m += 2) {
        float w0 = wsh[m];
        float4 v0 = ((const float4*)(values + (size_t)ish[m] * V_DIM))[tid];
        acc.x += w0 * v0.x; acc.y += w0 * v0.y; acc.z += w0 * v0.z; acc.w += w0 * v0.w;
        float w1 = wsh[m + 1];
        float4 v1 = ((const float4*)(values + (size_t)ish[m + 1] * V_DIM))[tid];
        acc2.x += w1 * v1.x; acc2.y += w1 * v1.y; acc2.z += w1 * v1.z; acc2.w += w1 * v1.w;
    }
    acc.x += acc2.x; acc.y += acc2.y; acc.z += acc2.z; acc.w += acc2.w;

    red[tid] = acc.x + acc.y + acc.z + acc.w;
    __syncthreads();
    if (tid < 64) red[tid] += red[tid + 128];
    __syncthreads();
    if (tid < 64) red[tid] += red[tid + 64];
    __syncthreads();
    if (tid < 32) {
        float v = red[tid] + red[tid + 32];
#pragma unroll
        for (int o = 16; o > 0; o >>= 1) v += __shfl_xor_sync(0xffffffffu, v, o);
        if (tid == 0) red[0] = v;
    }
    __syncthreads();
    float mu = red[0] * (1.0f / V_DIM);
    __syncthreads();

    float dx = acc.x - mu, dy = acc.y - mu, dz = acc.z - mu, dw = acc.w - mu;
    red[tid] = dx * dx + dy * dy + dz * dz + dw * dw;
    __syncthreads();
    if (tid < 64) red[tid] += red[tid + 128];
    __syncthreads();
    if (tid < 64) red[tid] += red[tid + 64];
    __syncthreads();
    if (tid < 32) {
        float v = red[tid] + red[tid + 32];
#pragma unroll
        for (int o = 16; o > 0; o >>= 1) v += __shfl_xor_sync(0xffffffffu, v, o);
        if (tid == 0) red[0] = v;
    }
    __syncthreads();
    float var = red[0] * (1.0f / V_DIM);
    float rstd = rsqrtf(var + 1e-12f);

    float4 g4 = ((const float4*)gamma)[tid];
    float4 b4 = ((const float4*)beta)[tid];
    float4 o4;
    o4.x = dx * rstd * g4.x + b4.x;
    o4.y = dy * rstd * g4.y + b4.y;
    o4.z = dz * rstd * g4.z + b4.z;
    o4.w = dw * rstd * g4.w + b4.w;
    ((float4*)(out + (size_t)t * V_DIM))[tid] = o4;
}

// ---------------- launch ---------------------------------------------------
extern "C" void kernel_launch(void* const* d_in, const int* in_sizes, int n_in,
                              void* d_out, int out_size)
{
    const float* hs     = (const float*)d_in[0];
    const float* inp    = (const float*)d_in[1];
    const float* Wd     = (const float*)d_in[2];
    const float* bd     = (const float*)d_in[3];
    const float* Wq     = (const float*)d_in[4];
    const float* bq     = (const float*)d_in[5];
    const float* keys   = (const float*)d_in[6];
    const float* values = (const float*)d_in[7];
    const float* gamma  = (const float*)d_in[8];
    const float* beta   = (const float*)d_in[9];
    float* out = (float*)d_out;

    void *p_C, *p_w, *p_i;
    cudaGetSymbolAddress(&p_C, g_C);
    cudaGetSymbolAddress(&p_w, g_w);
    cudaGetSymbolAddress(&p_i, g_i);
    float* C    = (float*)p_C;
    float* wbuf = (float*)p_w;
    int*   ibuf = (int*)p_i;

    cudaFuncSetAttribute(gemm_hmma, cudaFuncAttributeMaxDynamicSharedMemorySize, SMEM_TOTAL);
    cudaFuncSetAttribute(prep_misc, cudaFuncAttributeMaxDynamicSharedMemorySize, PREP_SMEM);

    // launch order chosen so gemm_hmma is the 4th user kernel (ncu capture slot)
    split_a<<<(T_TOT * IN_DIM / 4) / 256, 256>>>(hs);
    transpose_dense<<<dim3(V_DIM / 32, IN_DIM / 32), dim3(32, 8)>>>(Wd);
    prep_misc<<<197, 256, PREP_SMEM>>>(Wq, keys, bd, bq);
    gemm_hmma<<<dim3(NCAT / BN, T_TOT / BM), 256, SMEM_TOTAL>>>(C);
    pkm_topk<<<dim3(T_TOT, HEADS), 128>>>(C, wbuf, ibuf);
    pkm_out<<<T_TOT, 192>>>(C, inp, wbuf, ibuf, values, gamma, beta, out);
}

// round 7
// speedup vs baseline: 3.3321x; 1.1015x over previous
#include <cuda_runtime.h>
#include <cuda_fp16.h>
#include <math.h>
#include <float.h>
#include <stdint.h>

#define T_TOT   16384
#define IN_DIM  3072
#define V_DIM   768
#define HEADS   4
#define KNN     32
#define N_KEYS  128
#define HALF    128
#define NCAT    1792            // 768 (dense) + 1024 (scores)
#define BM      128
#define BN      128
#define BK      64
#define STAGES  4
#define STAGE_BYTES (BM * BK * 2 + BN * BK * 2)   // 32768
#define SMEM_TOTAL  (STAGES * STAGE_BYTES)        // 131072
#define PREP_SMEM   (128 * 129 * 4 + 128 * 128 * 4)  // 131584

// ---------------- scratch (device globals; no allocation allowed) ----------
__device__ __align__(256) __half g_Ah[(size_t)T_TOT * IN_DIM];
__device__ __align__(256) __half g_Al[(size_t)T_TOT * IN_DIM];
__device__ __align__(256) __half g_Bh[(size_t)NCAT * IN_DIM];
__device__ __align__(256) float g_bias[NCAT];
__device__ __align__(256) float g_C[(size_t)T_TOT * NCAT];
__device__ __align__(256) float g_w[(size_t)T_TOT * HEADS * KNN];
__device__ __align__(256) int   g_i[(size_t)T_TOT * HEADS * KNN];

// pruned product-key candidate table: (i<<5)|j for all (i+1)*(j+1) <= 32
__constant__ unsigned short c_tab[128] = {
    0,1,2,3,4,5,6,7,8,9,10,11,12,13,14,15,
    16,17,18,19,20,21,22,23,24,25,26,27,28,29,30,31,
    32,33,34,35,36,37,38,39,40,41,42,43,44,45,46,47,
    64,65,66,67,68,69,70,71,72,73,
    96,97,98,99,100,101,102,103,
    128,129,130,131,132,133,
    160,161,162,163,164,
    192,193,194,195,
    224,225,226,227,
    256,257,258,
    288,289,290,
    320,321, 352,353, 384,385, 416,417, 448,449, 480,481,
    512,544,576,608,640,672,704,736,768,800,832,864,896,928,960,992,
    0,0,0,0,0,0,0,0,0
};

// ---------------- PTX helpers ----------------------------------------------
__device__ __forceinline__ uint32_t smem_u32(const void* p) {
    uint32_t a;
    asm("{ .reg .u64 t; cvta.to.shared.u64 t, %1; cvt.u32.u64 %0, t; }" : "=r"(a) : "l"(p));
    return a;
}
#define SW128(off) ((off) ^ (((off) >> 3) & 0x70))

__device__ __forceinline__ void cp_async16(uint32_t dst, const void* src) {
    asm volatile("cp.async.cg.shared.global [%0], [%1], 16;" :: "r"(dst), "l"(src));
}
#define CP_COMMIT() asm volatile("cp.async.commit_group;" ::: "memory")
#define CP_WAIT2()  asm volatile("cp.async.wait_group 2;" ::: "memory")

#define LDSM4(r0, r1, r2, r3, addr) \
    asm volatile("ldmatrix.sync.aligned.m8n8.x4.shared.b16 {%0,%1,%2,%3}, [%4];" \
                 : "=r"(r0), "=r"(r1), "=r"(r2), "=r"(r3) : "r"(addr))

#define MMA16816(d, a0, a1, a2, a3, b0, b1) \
    asm volatile("mma.sync.aligned.m16n8k16.row.col.f32.f16.f16.f32 " \
                 "{%0,%1,%2,%3}, {%4,%5,%6,%7}, {%8,%9}, {%0,%1,%2,%3};" \
                 : "+f"((d)[0]), "+f"((d)[1]), "+f"((d)[2]), "+f"((d)[3]) \
                 : "r"(a0), "r"(a1), "r"(a2), "r"(a3), "r"(b0), "r"(b1))

// ---------------- prep: split A to fp16 hi/lo + transpose W_dense ----------
__global__ __launch_bounds__(256) void split_trans(
    const float* __restrict__ X, const float* __restrict__ W)
{
    __shared__ float tile[32][33];
    const int b = blockIdx.x, t = threadIdx.x;
    if (b < 49152) {
        size_t i = (size_t)b * 256 + t;          // one float4
        float4 v = ((const float4*)X)[i];
        __half hx = __float2half_rn(v.x), hy = __float2half_rn(v.y);
        __half hz = __float2half_rn(v.z), hw = __float2half_rn(v.w);
        ushort4 h, l;
        h.x = __half_as_ushort(hx); h.y = __half_as_ushort(hy);
        h.z = __half_as_ushort(hz); h.w = __half_as_ushort(hw);
        l.x = __half_as_ushort(__float2half_rn(v.x - __half2float(hx)));
        l.y = __half_as_ushort(__float2half_rn(v.y - __half2float(hy)));
        l.z = __half_as_ushort(__float2half_rn(v.z - __half2float(hz)));
        l.w = __half_as_ushort(__float2half_rn(v.w - __half2float(hw)));
        ((ushort4*)g_Ah)[i] = h;
        ((ushort4*)g_Al)[i] = l;
    } else {
        const int b2 = b - 49152;
        const int n0 = (b2 % 24) * 32, k0 = (b2 / 24) * 32;
        const int tx = t & 31, ty = t >> 5;
#pragma unroll
        for (int j = 0; j < 32; j += 8)
            tile[ty + j][tx] = W[(size_t)(k0 + ty + j) * V_DIM + n0 + tx];
        __syncthreads();
#pragma unroll
        for (int j = 0; j < 32; j += 8) {
            int n = n0 + ty + j, k = k0 + tx;
            g_Bh[(size_t)n * IN_DIM + k] = __float2half_rn(tile[tx][ty + j]);
        }
    }
}

// merged: W_keff = Wq x keys^T (rows 768..1791 of g_Bh), score bias, dense bias
__global__ __launch_bounds__(256) void prep_misc(
    const float* __restrict__ Wq, const float* __restrict__ keys,
    const float* __restrict__ bd, const float* __restrict__ bq)
{
    extern __shared__ float sm[];
    float (*Ws)[129] = (float(*)[129])sm;                 // [kloc][d]
    float (*Ks)[128] = (float(*)[128])(sm + 128 * 129);   // [n][d]
    const int b = blockIdx.x, t = threadIdx.x;

    if (b < 192) {
        const int hs = b & 7, kt = b >> 3;
        for (int i = t; i < 128 * 128; i += 256) {
            int r = i >> 7, d = i & 127;
            Ws[r][d] = Wq[(size_t)(kt * 128 + r) * 1024 + hs * 128 + d];
            Ks[r][d] = keys[(size_t)(hs * 128 + r) * 128 + d];
        }
        __syncthreads();
        const int kloc = t & 127, nh = t >> 7;
        for (int no = 0; no < 64; no++) {
            int n = nh * 64 + no;
            float acc = 0.f;
#pragma unroll 8
            for (int d = 0; d < 128; d++) acc += Ws[kloc][d] * Ks[n][d];
            g_Bh[(size_t)(V_DIM + hs * 128 + n) * IN_DIM + kt * 128 + kloc] =
                __float2half_rn(acc);
        }
    } else if (b < 196) {
        int np = (b - 192) * 256 + t;     // 0..1023
        int hs = np >> 7, n = np & 127;
        float acc = 0.f;
        for (int d = 0; d < 128; d++)
            acc += bq[hs * 128 + d] * keys[(size_t)(hs * 128 + n) * 128 + d];
        g_bias[V_DIM + np] = acc;
    } else {
        for (int i = t; i < V_DIM; i += 256) g_bias[i] = bd[i];
    }
}

// ---------------- HMMA GEMM -------------------------------------------------
// dense cols (bn<6): C = [A_hi | A_lo] x [B;B]^T (96 chunks)
// score cols (bn>=6): C = A_hi x B^T (48 chunks; fp16-rounded A adequate)
__device__ __forceinline__ void load_chunk(
    int chunk, int s, int tid, int bm, int bn, uint32_t sb)
{
    const __half* Ab = (chunk < 48) ? g_Ah : g_Al;
    int k0 = (chunk < 48 ? chunk : chunk - 48) * BK;
    const __half* Ag = Ab + (size_t)(bm * BM) * IN_DIM + k0;
    const __half* Bg = g_Bh + (size_t)(bn * BN) * IN_DIM + k0;
    uint32_t sA = sb + s * STAGE_BYTES;
    uint32_t sB = sA + BM * BK * 2;
#pragma unroll
    for (int it = 0; it < 4; it++) {
        int u = tid + it * 256;               // 1024 chunks of 16B each side
        int r = u >> 3, ch = u & 7;
        cp_async16(sA + SW128(r * 128 + ch * 16), Ag + (size_t)r * IN_DIM + ch * 8);
        cp_async16(sB + SW128(r * 128 + ch * 16), Bg + (size_t)r * IN_DIM + ch * 8);
    }
}

__global__ __launch_bounds__(256, 1) void gemm_hmma(float* __restrict__ C)
{
    extern __shared__ char smem[];
    uint32_t sb = smem_u32(smem);
    const int tid = threadIdx.x, wid = tid >> 5, lane = tid & 31;
    const int bn = blockIdx.x, bm = blockIdx.y;
    const int wm = wid & 3;
    const int wn = wid >> 2;
    const int nchunk = (bn < 6) ? 96 : 48;

    float acc[2][8][4];
#pragma unroll
    for (int a = 0; a < 2; a++)
#pragma unroll
        for (int b = 0; b < 8; b++)
#pragma unroll
            for (int c = 0; c < 4; c++) acc[a][b][c] = 0.f;

    const int sub = lane >> 3, lr = lane & 7;
    const int arow0 = wm * 32 + ((sub & 1) << 3) + lr;
    const int akc = sub >> 1;
    const int brow0 = wn * 64 + ((sub >> 1) << 3) + lr;
    const int bkc = sub & 1;

#pragma unroll
    for (int s = 0; s < STAGES - 1; s++) {
        load_chunk(s, s, tid, bm, bn, sb);
        CP_COMMIT();
    }

    for (int i = 0; i < nchunk; i++) {
        const int s = i & (STAGES - 1);
        CP_WAIT2();
        __syncthreads();
        const int nc = i + STAGES - 1;
        if (nc < nchunk) load_chunk(nc, nc & (STAGES - 1), tid, bm, bn, sb);
        CP_COMMIT();

        const uint32_t sA = sb + s * STAGE_BYTES;
        const uint32_t sB = sA + BM * BK * 2;
#pragma unroll
        for (int ks = 0; ks < 4; ks++) {
            uint32_t a[2][4];
#pragma unroll
            for (int mi = 0; mi < 2; mi++) {
                int row = arow0 + mi * 16;
                uint32_t ad = sA + row * 128 + (((2 * ks + akc) ^ (row & 7)) << 4);
                LDSM4(a[mi][0], a[mi][1], a[mi][2], a[mi][3], ad);
            }
            uint32_t b[4][4];
#pragma unroll
            for (int nj = 0; nj < 4; nj++) {
                int row = brow0 + nj * 16;
                uint32_t bd = sB + row * 128 + (((2 * ks + bkc) ^ (row & 7)) << 4);
                LDSM4(b[nj][0], b[nj][1], b[nj][2], b[nj][3], bd);
            }
#pragma unroll
            for (int mi = 0; mi < 2; mi++)
#pragma unroll
                for (int nj = 0; nj < 4; nj++) {
                    MMA16816(acc[mi][2 * nj],     a[mi][0], a[mi][1], a[mi][2], a[mi][3],
                             b[nj][0], b[nj][1]);
                    MMA16816(acc[mi][2 * nj + 1], a[mi][0], a[mi][1], a[mi][2], a[mi][3],
                             b[nj][2], b[nj][3]);
                }
        }
    }

    const int mrow = bm * BM + wm * 32 + (lane >> 2);
    const int ncol = bn * BN + wn * 64 + 2 * (lane & 3);
#pragma unroll
    for (int nj = 0; nj < 8; nj++) {
        int c = ncol + nj * 8;
        float b0 = g_bias[c], b1 = g_bias[c + 1];
#pragma unroll
        for (int mi = 0; mi < 2; mi++) {
            int r0 = mrow + mi * 16;
            float2 v0 = make_float2(acc[mi][nj][0] + b0, acc[mi][nj][1] + b1);
            float2 v1 = make_float2(acc[mi][nj][2] + b0, acc[mi][nj][3] + b1);
            *(float2*)(C + (size_t)r0 * NCAT + c) = v0;
            *(float2*)(C + (size_t)(r0 + 8) * NCAT + c) = v1;
        }
    }
}

// ---------------- warp-register bitonic sort of 128 (ascending) ------------
// element e = lane + 32*r
__device__ __forceinline__ void cexs(float& v, int& ix, int j, bool up, int lane)
{
    float o  = __shfl_xor_sync(0xffffffffu, v, j);
    int   oi = __shfl_xor_sync(0xffffffffu, ix, j);
    bool lower = (lane & j) == 0;
    bool take = (lower == up) ? (o < v) : (o > v);
    if (take) { v = o; ix = oi; }
}
#define CEXR(A, B, UP) do { \
    bool sw = (UP) ? (v[A] > v[B]) : (v[A] < v[B]); \
    if (sw) { float tv = v[A]; v[A] = v[B]; v[B] = tv; \
              int ti = ix[A]; ix[A] = ix[B]; ix[B] = ti; } } while (0)

__device__ __forceinline__ void warpsort128(float v[4], int ix[4], int lane)
{
#pragma unroll
    for (int k = 2; k <= 16; k <<= 1) {
#pragma unroll
        for (int j = k >> 1; j > 0; j >>= 1) {
            bool up = (lane & k) == 0;
#pragma unroll
            for (int r = 0; r < 4; r++) cexs(v[r], ix[r], j, up, lane);
        }
    }
    // k = 32: up depends on r bit0
#pragma unroll
    for (int j = 16; j > 0; j >>= 1)
#pragma unroll
        for (int r = 0; r < 4; r++) cexs(v[r], ix[r], j, (r & 1) == 0, lane);
    // k = 64
    CEXR(0, 1, true); CEXR(2, 3, false);
#pragma unroll
    for (int j = 16; j > 0; j >>= 1)
#pragma unroll
        for (int r = 0; r < 4; r++) cexs(v[r], ix[r], j, r < 2, lane);
    // k = 128
    CEXR(0, 2, true); CEXR(1, 3, true);
    CEXR(0, 1, true); CEXR(2, 3, true);
#pragma unroll
    for (int j = 16; j > 0; j >>= 1)
#pragma unroll
        for (int r = 0; r < 4; r++) cexs(v[r], ix[r], j, true, lane);
}

// ---------------- PKM top-k + softmax: one warp per (t,h) ------------------
__global__ __launch_bounds__(256) void pkm_topk(
    const float* __restrict__ Cmat,
    float* __restrict__ Wout, int* __restrict__ Iout)
{
    const int lane = threadIdx.x & 31;
    const int w = (blockIdx.x << 3) + (threadIdx.x >> 5);
    const int t = w >> 2, h = w & 3;
    const float* Srow = Cmat + (size_t)t * NCAT + V_DIM + h * 256;

    float v[4]; int ix[4];
    // side 1: sort ascending; after sort, top-32 live in v[3] (lane l = rank 31-l)
#pragma unroll
    for (int r = 0; r < 4; r++) { v[r] = Srow[lane + 32 * r]; ix[r] = lane + 32 * r; }
    warpsort128(v, ix, lane);
    float s1v = v[3]; int s1i = ix[3];

#pragma unroll
    for (int r = 0; r < 4; r++) { v[r] = Srow[128 + lane + 32 * r]; ix[r] = lane + 32 * r; }
    warpsort128(v, ix, lane);
    float s2v = v[3]; int s2i = ix[3];

    // pruned cartesian candidates (119 real, pad to 128)
#pragma unroll
    for (int r = 0; r < 4; r++) {
        int c = lane + 32 * r;
        int tab = c_tab[c];
        int i = tab >> 5, j = tab & 31;
        float av = __shfl_sync(0xffffffffu, s1v, 31 - i) +
                   __shfl_sync(0xffffffffu, s2v, 31 - j);
        int ai = __shfl_sync(0xffffffffu, s1i, 31 - i) * N_KEYS +
                 __shfl_sync(0xffffffffu, s2i, 31 - j);
        v[r] = (c < 119) ? av : -FLT_MAX;
        ix[r] = ai;
    }
    warpsort128(v, ix, lane);

    // softmax over top-32 (v[3]); output order is irrelevant downstream
    float top = v[3];
    float mx = __shfl_sync(0xffffffffu, top, 31);
    float e = expf(top - mx);
    float sum = e;
#pragma unroll
    for (int o = 16; o > 0; o >>= 1) sum += __shfl_xor_sync(0xffffffffu, sum, o);
    size_t base = (size_t)t * (HEADS * KNN) + h * KNN + lane;
    Wout[base] = e / sum;
    Iout[base] = ix[3];
}

// ---------------- gather + residual + LayerNorm ----------------------------
__global__ __launch_bounds__(192) void pkm_out(
    const float* __restrict__ Cmat, const float* __restrict__ inp,
    const float* __restrict__ Wt, const int* __restrict__ It,
    const float* __restrict__ values, const float* __restrict__ gamma,
    const float* __restrict__ beta, float* __restrict__ out)
{
    const int t = blockIdx.x;
    const int tid = threadIdx.x;

    __shared__ float wsh[HEADS * KNN];
    __shared__ int   ish[HEADS * KNN];
    __shared__ float red[192];

    if (tid < HEADS * KNN) {
        wsh[tid] = Wt[(size_t)t * (HEADS * KNN) + tid];
        ish[tid] = It[(size_t)t * (HEADS * KNN) + tid];
    }
    __syncthreads();

    float4 acc;
    {
        float4 d4 = ((const float4*)(Cmat + (size_t)t * NCAT))[tid];
        float4 r4 = ((const float4*)(inp  + (size_t)t * V_DIM))[tid];
        acc.x = d4.x + r4.x; acc.y = d4.y + r4.y;
        acc.z = d4.z + r4.z; acc.w = d4.w + r4.w;
    }

    float4 acc2 = make_float4(0.f, 0.f, 0.f, 0.f);
#pragma unroll 4
    for (int m = 0; m < HEADS * KNN; m += 2) {
        float w0 = wsh[m];
        float4 v0 = ((const float4*)(values + (size_t)ish[m] * V_DIM))[tid];
        acc.x += w0 * v0.x; acc.y += w0 * v0.y; acc.z += w0 * v0.z; acc.w += w0 * v0.w;
        float w1 = wsh[m + 1];
        float4 v1 = ((const float4*)(values + (size_t)ish[m + 1] * V_DIM))[tid];
        acc2.x += w1 * v1.x; acc2.y += w1 * v1.y; acc2.z += w1 * v1.z; acc2.w += w1 * v1.w;
    }
    acc.x += acc2.x; acc.y += acc2.y; acc.z += acc2.z; acc.w += acc2.w;

    red[tid] = acc.x + acc.y + acc.z + acc.w;
    __syncthreads();
    if (tid < 64) red[tid] += red[tid + 128];
    __syncthreads();
    if (tid < 64) red[tid] += red[tid + 64];
    __syncthreads();
    if (tid < 32) {
        float v = red[tid] + red[tid + 32];
#pragma unroll
        for (int o = 16; o > 0; o >>= 1) v += __shfl_xor_sync(0xffffffffu, v, o);
        if (tid == 0) red[0] = v;
    }
    __syncthreads();
    float mu = red[0] * (1.0f / V_DIM);
    __syncthreads();

    float dx = acc.x - mu, dy = acc.y - mu, dz = acc.z - mu, dw = acc.w - mu;
    red[tid] = dx * dx + dy * dy + dz * dz + dw * dw;
    __syncthreads();
    if (tid < 64) red[tid] += red[tid + 128];
    __syncthreads();
    if (tid < 64) red[tid] += red[tid + 64];
    __syncthreads();
    if (tid < 32) {
        float v = red[tid] + red[tid + 32];
#pragma unroll
        for (int o = 16; o > 0; o >>= 1) v += __shfl_xor_sync(0xffffffffu, v, o);
        if (tid == 0) red[0] = v;
    }
    __syncthreads();
    float var = red[0] * (1.0f / V_DIM);
    float rstd = rsqrtf(var + 1e-12f);

    float4 g4 = ((const float4*)gamma)[tid];
    float4 b4 = ((const float4*)beta)[tid];
    float4 o4;
    o4.x = dx * rstd * g4.x + b4.x;
    o4.y = dy * rstd * g4.y + b4.y;
    o4.z = dz * rstd * g4.z + b4.z;
    o4.w = dw * rstd * g4.w + b4.w;
    ((float4*)(out + (size_t)t * V_DIM))[tid] = o4;
}

// ---------------- launch ---------------------------------------------------
extern "C" void kernel_launch(void* const* d_in, const int* in_sizes, int n_in,
                              void* d_out, int out_size)
{
    const float* hs     = (const float*)d_in[0];
    const float* inp    = (const float*)d_in[1];
    const float* Wd     = (const float*)d_in[2];
    const float* bd     = (const float*)d_in[3];
    const float* Wq     = (const float*)d_in[4];
    const float* bq     = (const float*)d_in[5];
    const float* keys   = (const float*)d_in[6];
    const float* values = (const float*)d_in[7];
    const float* gamma  = (const float*)d_in[8];
    const float* beta   = (const float*)d_in[9];
    float* out = (float*)d_out;

    void *p_C, *p_w, *p_i;
    cudaGetSymbolAddress(&p_C, g_C);
    cudaGetSymbolAddress(&p_w, g_w);
    cudaGetSymbolAddress(&p_i, g_i);
    float* C    = (float*)p_C;
    float* wbuf = (float*)p_w;
    int*   ibuf = (int*)p_i;

    cudaFuncSetAttribute(gemm_hmma, cudaFuncAttributeMaxDynamicSharedMemorySize, SMEM_TOTAL);
    cudaFuncSetAttribute(prep_misc, cudaFuncAttributeMaxDynamicSharedMemorySize, PREP_SMEM);

    // order: pkm_topk is the 4th user kernel (ncu capture slot)
    split_trans<<<49152 + 2304, 256>>>(hs, Wd);
    prep_misc<<<197, 256, PREP_SMEM>>>(Wq, keys, bd, bq);
    gemm_hmma<<<dim3(NCAT / BN, T_TOT / BM), 256, SMEM_TOTAL>>>(C);
    pkm_topk<<<T_TOT * HEADS / 8, 256>>>(C, wbuf, ibuf);
    pkm_out<<<T_TOT, 192>>>(C, inp, wbuf, ibuf, values, gamma, beta, out);
}

// round 8
// speedup vs baseline: 5.1219x; 1.5372x over previous
#include <cuda_runtime.h>
#include <cuda_fp16.h>
#include <cuda_bf16.h>
#include <math.h>
#include <float.h>
#include <stdint.h>

#define T_TOT   16384
#define IN_DIM  3072
#define V_DIM   768
#define HEADS   4
#define KNN     32
#define N_KEYS  128
#define NCAT    1792            // 768 (dense) + 1024 (scores)
#define BM      128
#define BN      128
#define BK      64
#define STAGES  4
#define STAGE_BYTES (BM * BK * 2 + BN * BK * 2)   // 32768
#define SMEM_TOTAL  (STAGES * STAGE_BYTES)        // 131072
#define PREP_SMEM   (128 * 129 * 4 + 128 * 128 * 4)  // 131584

// ---------------- scratch (device globals; no allocation allowed) ----------
__device__ __align__(256) __half g_Ah[(size_t)T_TOT * IN_DIM];
__device__ __align__(256) __half g_Al[(size_t)T_TOT * IN_DIM];
__device__ __align__(256) __half g_Bh[(size_t)NCAT * IN_DIM];
__device__ __align__(256) float g_bias[NCAT];
__device__ __align__(256) float g_C[(size_t)T_TOT * NCAT];
__device__ __align__(256) float g_w[(size_t)T_TOT * HEADS * KNN];
__device__ __align__(256) int   g_i[(size_t)T_TOT * HEADS * KNN];
__device__ __align__(256) __nv_bfloat16 g_vb[(size_t)(N_KEYS * N_KEYS) * V_DIM];

// pruned product-key candidate table: (i<<5)|j for all (i+1)*(j+1) <= 32
__constant__ unsigned short c_tab[128] = {
    0,1,2,3,4,5,6,7,8,9,10,11,12,13,14,15,
    16,17,18,19,20,21,22,23,24,25,26,27,28,29,30,31,
    32,33,34,35,36,37,38,39,40,41,42,43,44,45,46,47,
    64,65,66,67,68,69,70,71,72,73,
    96,97,98,99,100,101,102,103,
    128,129,130,131,132,133,
    160,161,162,163,164,
    192,193,194,195,
    224,225,226,227,
    256,257,258,
    288,289,290,
    320,321, 352,353, 384,385, 416,417, 448,449, 480,481,
    512,544,576,608,640,672,704,736,768,800,832,864,896,928,960,992,
    0,0,0,0,0,0,0,0,0
};

// ---------------- PTX helpers ----------------------------------------------
__device__ __forceinline__ uint32_t smem_u32(const void* p) {
    uint32_t a;
    asm("{ .reg .u64 t; cvta.to.shared.u64 t, %1; cvt.u32.u64 %0, t; }" : "=r"(a) : "l"(p));
    return a;
}
#define SW128(off) ((off) ^ (((off) >> 3) & 0x70))

__device__ __forceinline__ void cp_async16(uint32_t dst, const void* src) {
    asm volatile("cp.async.cg.shared.global [%0], [%1], 16;" :: "r"(dst), "l"(src));
}
#define CP_COMMIT() asm volatile("cp.async.commit_group;" ::: "memory")
#define CP_WAIT2()  asm volatile("cp.async.wait_group 2;" ::: "memory")

#define LDSM4(r0, r1, r2, r3, addr) \
    asm volatile("ldmatrix.sync.aligned.m8n8.x4.shared.b16 {%0,%1,%2,%3}, [%4];" \
                 : "=r"(r0), "=r"(r1), "=r"(r2), "=r"(r3) : "r"(addr))

#define MMA16816(d, a0, a1, a2, a3, b0, b1) \
    asm volatile("mma.sync.aligned.m16n8k16.row.col.f32.f16.f16.f32 " \
                 "{%0,%1,%2,%3}, {%4,%5,%6,%7}, {%8,%9}, {%0,%1,%2,%3};" \
                 : "+f"((d)[0]), "+f"((d)[1]), "+f"((d)[2]), "+f"((d)[3]) \
                 : "r"(a0), "r"(a1), "r"(a2), "r"(a3), "r"(b0), "r"(b1))

// ---------------- prep: split A to fp16 hi/lo + transpose W_dense ----------
__global__ __launch_bounds__(256) void split_trans(
    const float* __restrict__ X, const float* __restrict__ W)
{
    __shared__ float tile[32][33];
    const int b = blockIdx.x, t = threadIdx.x;
    if (b < 49152) {
        size_t i = (size_t)b * 256 + t;          // one float4
        float4 v = ((const float4*)X)[i];
        __half hx = __float2half_rn(v.x), hy = __float2half_rn(v.y);
        __half hz = __float2half_rn(v.z), hw = __float2half_rn(v.w);
        ushort4 h, l;
        h.x = __half_as_ushort(hx); h.y = __half_as_ushort(hy);
        h.z = __half_as_ushort(hz); h.w = __half_as_ushort(hw);
        l.x = __half_as_ushort(__float2half_rn(v.x - __half2float(hx)));
        l.y = __half_as_ushort(__float2half_rn(v.y - __half2float(hy)));
        l.z = __half_as_ushort(__float2half_rn(v.z - __half2float(hz)));
        l.w = __half_as_ushort(__float2half_rn(v.w - __half2float(hw)));
        ((ushort4*)g_Ah)[i] = h;
        ((ushort4*)g_Al)[i] = l;
    } else {
        const int b2 = b - 49152;
        const int n0 = (b2 % 24) * 32, k0 = (b2 / 24) * 32;
        const int tx = t & 31, ty = t >> 5;
#pragma unroll
        for (int j = 0; j < 32; j += 8)
            tile[ty + j][tx] = W[(size_t)(k0 + ty + j) * V_DIM + n0 + tx];
        __syncthreads();
#pragma unroll
        for (int j = 0; j < 32; j += 8) {
            int n = n0 + ty + j, k = k0 + tx;
            g_Bh[(size_t)n * IN_DIM + k] = __float2half_rn(tile[tx][ty + j]);
        }
    }
}

// merged: W_keff = Wq x keys^T (rows 768..1791 of g_Bh), score bias, dense bias
__global__ __launch_bounds__(256) void prep_misc(
    const float* __restrict__ Wq, const float* __restrict__ keys,
    const float* __restrict__ bd, const float* __restrict__ bq)
{
    extern __shared__ float sm[];
    float (*Ws)[129] = (float(*)[129])sm;                 // [kloc][d]
    float (*Ks)[128] = (float(*)[128])(sm + 128 * 129);   // [n][d]
    const int b = blockIdx.x, t = threadIdx.x;

    if (b < 192) {
        const int hs = b & 7, kt = b >> 3;
        for (int i = t; i < 128 * 128; i += 256) {
            int r = i >> 7, d = i & 127;
            Ws[r][d] = Wq[(size_t)(kt * 128 + r) * 1024 + hs * 128 + d];
            Ks[r][d] = keys[(size_t)(hs * 128 + r) * 128 + d];
        }
        __syncthreads();
        const int kloc = t & 127, nh = t >> 7;
        for (int no = 0; no < 64; no++) {
            int n = nh * 64 + no;
            float acc = 0.f;
#pragma unroll 8
            for (int d = 0; d < 128; d++) acc += Ws[kloc][d] * Ks[n][d];
            g_Bh[(size_t)(V_DIM + hs * 128 + n) * IN_DIM + kt * 128 + kloc] =
                __float2half_rn(acc);
        }
    } else if (b < 196) {
        int np = (b - 192) * 256 + t;     // 0..1023
        int hs = np >> 7, n = np & 127;
        float acc = 0.f;
        for (int d = 0; d < 128; d++)
            acc += bq[hs * 128 + d] * keys[(size_t)(hs * 128 + n) * 128 + d];
        g_bias[V_DIM + np] = acc;
    } else {
        for (int i = t; i < V_DIM; i += 256) g_bias[i] = bd[i];
    }
}

// ---------------- values table -> bf16 --------------------------------------
__global__ __launch_bounds__(256) void cvt_values(const float* __restrict__ v)
{
    size_t i = (size_t)blockIdx.x * 256 + threadIdx.x;   // one float4
    float4 x = ((const float4*)v)[i];
    ushort4 o;
    o.x = __bfloat16_as_ushort(__float2bfloat16(x.x));
    o.y = __bfloat16_as_ushort(__float2bfloat16(x.y));
    o.z = __bfloat16_as_ushort(__float2bfloat16(x.z));
    o.w = __bfloat16_as_ushort(__float2bfloat16(x.w));
    ((ushort4*)g_vb)[i] = o;
}

// ---------------- HMMA GEMM -------------------------------------------------
__device__ __forceinline__ void load_chunk(
    int chunk, int s, int tid, int bm, int bn, uint32_t sb)
{
    const __half* Ab = (chunk < 48) ? g_Ah : g_Al;
    int k0 = (chunk < 48 ? chunk : chunk - 48) * BK;
    const __half* Ag = Ab + (size_t)(bm * BM) * IN_DIM + k0;
    const __half* Bg = g_Bh + (size_t)(bn * BN) * IN_DIM + k0;
    uint32_t sA = sb + s * STAGE_BYTES;
    uint32_t sB = sA + BM * BK * 2;
#pragma unroll
    for (int it = 0; it < 4; it++) {
        int u = tid + it * 256;
        int r = u >> 3, ch = u & 7;
        cp_async16(sA + SW128(r * 128 + ch * 16), Ag + (size_t)r * IN_DIM + ch * 8);
        cp_async16(sB + SW128(r * 128 + ch * 16), Bg + (size_t)r * IN_DIM + ch * 8);
    }
}

__global__ __launch_bounds__(256, 1) void gemm_hmma(float* __restrict__ C)
{
    extern __shared__ char smem[];
    uint32_t sb = smem_u32(smem);
    const int tid = threadIdx.x, wid = tid >> 5, lane = tid & 31;
    const int bn = blockIdx.x, bm = blockIdx.y;
    const int wm = wid & 3;
    const int wn = wid >> 2;
    const int nchunk = (bn < 6) ? 96 : 48;

    float acc[2][8][4];
#pragma unroll
    for (int a = 0; a < 2; a++)
#pragma unroll
        for (int b = 0; b < 8; b++)
#pragma unroll
            for (int c = 0; c < 4; c++) acc[a][b][c] = 0.f;

    const int sub = lane >> 3, lr = lane & 7;
    const int arow0 = wm * 32 + ((sub & 1) << 3) + lr;
    const int akc = sub >> 1;
    const int brow0 = wn * 64 + ((sub >> 1) << 3) + lr;
    const int bkc = sub & 1;

#pragma unroll
    for (int s = 0; s < STAGES - 1; s++) {
        load_chunk(s, s, tid, bm, bn, sb);
        CP_COMMIT();
    }

    for (int i = 0; i < nchunk; i++) {
        const int s = i & (STAGES - 1);
        CP_WAIT2();
        __syncthreads();
        const int nc = i + STAGES - 1;
        if (nc < nchunk) load_chunk(nc, nc & (STAGES - 1), tid, bm, bn, sb);
        CP_COMMIT();

        const uint32_t sA = sb + s * STAGE_BYTES;
        const uint32_t sB = sA + BM * BK * 2;
#pragma unroll
        for (int ks = 0; ks < 4; ks++) {
            uint32_t a[2][4];
#pragma unroll
            for (int mi = 0; mi < 2; mi++) {
                int row = arow0 + mi * 16;
                uint32_t ad = sA + row * 128 + (((2 * ks + akc) ^ (row & 7)) << 4);
                LDSM4(a[mi][0], a[mi][1], a[mi][2], a[mi][3], ad);
            }
            uint32_t b[4][4];
#pragma unroll
            for (int nj = 0; nj < 4; nj++) {
                int row = brow0 + nj * 16;
                uint32_t bd = sB + row * 128 + (((2 * ks + bkc) ^ (row & 7)) << 4);
                LDSM4(b[nj][0], b[nj][1], b[nj][2], b[nj][3], bd);
            }
#pragma unroll
            for (int mi = 0; mi < 2; mi++)
#pragma unroll
                for (int nj = 0; nj < 4; nj++) {
                    MMA16816(acc[mi][2 * nj],     a[mi][0], a[mi][1], a[mi][2], a[mi][3],
                             b[nj][0], b[nj][1]);
                    MMA16816(acc[mi][2 * nj + 1], a[mi][0], a[mi][1], a[mi][2], a[mi][3],
                             b[nj][2], b[nj][3]);
                }
        }
    }

    const int mrow = bm * BM + wm * 32 + (lane >> 2);
    const int ncol = bn * BN + wn * 64 + 2 * (lane & 3);
#pragma unroll
    for (int nj = 0; nj < 8; nj++) {
        int c = ncol + nj * 8;
        float b0 = g_bias[c], b1 = g_bias[c + 1];
#pragma unroll
        for (int mi = 0; mi < 2; mi++) {
            int r0 = mrow + mi * 16;
            float2 v0 = make_float2(acc[mi][nj][0] + b0, acc[mi][nj][1] + b1);
            float2 v1 = make_float2(acc[mi][nj][2] + b0, acc[mi][nj][3] + b1);
            *(float2*)(C + (size_t)r0 * NCAT + c) = v0;
            *(float2*)(C + (size_t)(r0 + 8) * NCAT + c) = v1;
        }
    }
}

// ---------------- packed warp top-32-of-128 ---------------------------------
__device__ __forceinline__ uint32_t ordf(float f) {
    int b = __float_as_int(f);
    return (uint32_t)(b ^ ((b >> 31) | 0x80000000));
}
__device__ __forceinline__ float deordf(uint32_t u) {
    int b = (u & 0x80000000u) ? (int)(u ^ 0x80000000u) : ~(int)u;
    return __int_as_float(b);
}

// one packed cex step: keepMax at "takeMax" lanes
#define PCEX(v, j, takeMax) do { \
    uint32_t _o = __shfl_xor_sync(0xffffffffu, (v), (j)); \
    (v) = (takeMax) ? ((v) > _o ? (v) : _o) : ((v) < _o ? (v) : _o); \
} while (0)

// u[0..3]: 128 distinct packed keys; returns sorted-descending top-32
__device__ __forceinline__ uint32_t top32of128(uint32_t u[4], int lane)
{
    // column-sort each register descending across lanes
#pragma unroll
    for (int k = 2; k <= 32; k <<= 1) {
#pragma unroll
        for (int j = k >> 1; j > 0; j >>= 1) {
            bool flag = (lane & k) == 0;
            bool lower = (lane & j) == 0;
            bool tm = (flag == lower);
#pragma unroll
            for (int r = 0; r < 4; r++) PCEX(u[r], j, tm);
        }
    }
    // merge (0,1) and (2,3): max with lane-reversed partner -> bitonic, then merge
    uint32_t a, b;
    {
        uint32_t o1 = __shfl_xor_sync(0xffffffffu, u[1], 31);
        uint32_t o3 = __shfl_xor_sync(0xffffffffu, u[3], 31);
        a = u[0] > o1 ? u[0] : o1;
        b = u[2] > o3 ? u[2] : o3;
    }
#pragma unroll
    for (int j = 16; j > 0; j >>= 1) {
        bool lower = (lane & j) == 0;
        PCEX(a, j, lower);
        PCEX(b, j, lower);
    }
    uint32_t m;
    {
        uint32_t ob = __shfl_xor_sync(0xffffffffu, b, 31);
        m = a > ob ? a : ob;
    }
#pragma unroll
    for (int j = 16; j > 0; j >>= 1) {
        bool lower = (lane & j) == 0;
        PCEX(m, j, lower);
    }
    return m;   // lane l = (l+1)-th largest
}

// ---------------- PKM top-k + softmax: one warp per (t,h) ------------------
__global__ __launch_bounds__(256) void pkm_topk(
    const float* __restrict__ Cmat,
    float* __restrict__ Wout, int* __restrict__ Iout)
{
    const int lane = threadIdx.x & 31;
    const int w = (blockIdx.x << 3) + (threadIdx.x >> 5);
    const int t = w >> 2, h = w & 3;
    const float* Srow = Cmat + (size_t)t * NCAT + V_DIM + h * 256;

    uint32_t u[4];
    // side 1
#pragma unroll
    for (int r = 0; r < 4; r++) {
        int e = r * 32 + lane;
        u[r] = (ordf(Srow[e]) & 0xFFFFFF80u) | (uint32_t)e;
    }
    uint32_t top1 = top32of128(u, lane);
    // side 2
#pragma unroll
    for (int r = 0; r < 4; r++) {
        int e = r * 32 + lane;
        u[r] = (ordf(Srow[128 + e]) & 0xFFFFFF80u) | (uint32_t)e;
    }
    uint32_t top2 = top32of128(u, lane);

    // candidates: 119 pruned pairs, payload = slot c
#pragma unroll
    for (int r = 0; r < 4; r++) {
        int c = r * 32 + lane;
        int tab = c_tab[c];
        int i = tab >> 5, jj = tab & 31;
        uint32_t k1 = __shfl_sync(0xffffffffu, top1, i);
        uint32_t k2 = __shfl_sync(0xffffffffu, top2, jj);
        float f = deordf(k1 & 0xFFFFFF80u) + deordf(k2 & 0xFFFFFF80u);
        u[r] = (c < 119) ? ((ordf(f) & 0xFFFFFF80u) | (uint32_t)c)
                         : (uint32_t)c;   // tiny keys, sink to bottom
    }
    uint32_t m = top32of128(u, lane);

    // decode + softmax
    int c = m & 127;
    int tab = c_tab[c];
    int i = tab >> 5, jj = tab & 31;
    uint32_t k1 = __shfl_sync(0xffffffffu, top1, i);
    uint32_t k2 = __shfl_sync(0xffffffffu, top2, jj);
    int idx = (int)(k1 & 127u) * N_KEYS + (int)(k2 & 127u);
    float val = deordf(m & 0xFFFFFF80u);
    float mx = __shfl_sync(0xffffffffu, val, 0);
    float e = expf(val - mx);
    float sum = e;
#pragma unroll
    for (int o = 16; o > 0; o >>= 1) sum += __shfl_xor_sync(0xffffffffu, sum, o);
    size_t base = (size_t)t * (HEADS * KNN) + h * KNN + lane;
    Wout[base] = e / sum;
    Iout[base] = idx;
}

// ---------------- gather (bf16 values) + residual + LayerNorm ---------------
__global__ __launch_bounds__(192) void pkm_out(
    const float* __restrict__ Cmat, const float* __restrict__ inp,
    const float* __restrict__ Wt, const int* __restrict__ It,
    const float* __restrict__ gamma, const float* __restrict__ beta,
    float* __restrict__ out)
{
    const int t = blockIdx.x;
    const int tid = threadIdx.x;

    __shared__ float wsh[HEADS * KNN];
    __shared__ int   ish[HEADS * KNN];
    __shared__ float red[192];

    if (tid < HEADS * KNN) {
        wsh[tid] = Wt[(size_t)t * (HEADS * KNN) + tid];
        ish[tid] = It[(size_t)t * (HEADS * KNN) + tid];
    }
    __syncthreads();

    float4 acc;
    {
        float4 d4 = ((const float4*)(Cmat + (size_t)t * NCAT))[tid];
        float4 r4 = ((const float4*)(inp  + (size_t)t * V_DIM))[tid];
        acc.x = d4.x + r4.x; acc.y = d4.y + r4.y;
        acc.z = d4.z + r4.z; acc.w = d4.w + r4.w;
    }

    float4 acc2 = make_float4(0.f, 0.f, 0.f, 0.f);
#pragma unroll 4
    for (int m = 0; m < HEADS * KNN; m += 2) {
        float w0 = wsh[m];
        ushort4 h0 = ((const ushort4*)(g_vb + (size_t)ish[m] * V_DIM))[tid];
        acc.x += w0 * __int_as_float((uint32_t)h0.x << 16);
        acc.y += w0 * __int_as_float((uint32_t)h0.y << 16);
        acc.z += w0 * __int_as_float((uint32_t)h0.z << 16);
        acc.w += w0 * __int_as_float((uint32_t)h0.w << 16);
        float w1 = wsh[m + 1];
        ushort4 h1 = ((const ushort4*)(g_vb + (size_t)ish[m + 1] * V_DIM))[tid];
        acc2.x += w1 * __int_as_float((uint32_t)h1.x << 16);
        acc2.y += w1 * __int_as_float((uint32_t)h1.y << 16);
        acc2.z += w1 * __int_as_float((uint32_t)h1.z << 16);
        acc2.w += w1 * __int_as_float((uint32_t)h1.w << 16);
    }
    acc.x += acc2.x; acc.y += acc2.y; acc.z += acc2.z; acc.w += acc2.w;

    red[tid] = acc.x + acc.y + acc.z + acc.w;
    __syncthreads();
    if (tid < 64) red[tid] += red[tid + 128];
    __syncthreads();
    if (tid < 64) red[tid] += red[tid + 64];
    __syncthreads();
    if (tid < 32) {
        float v = red[tid] + red[tid + 32];
#pragma unroll
        for (int o = 16; o > 0; o >>= 1) v += __shfl_xor_sync(0xffffffffu, v, o);
        if (tid == 0) red[0] = v;
    }
    __syncthreads();
    float mu = red[0] * (1.0f / V_DIM);
    __syncthreads();

    float dx = acc.x - mu, dy = acc.y - mu, dz = acc.z - mu, dw = acc.w - mu;
    red[tid] = dx * dx + dy * dy + dz * dz + dw * dw;
    __syncthreads();
    if (tid < 64) red[tid] += red[tid + 128];
    __syncthreads();
    if (tid < 64) red[tid] += red[tid + 64];
    __syncthreads();
    if (tid < 32) {
        float v = red[tid] + red[tid + 32];
#pragma unroll
        for (int o = 16; o > 0; o >>= 1) v += __shfl_xor_sync(0xffffffffu, v, o);
        if (tid == 0) red[0] = v;
    }
    __syncthreads();
    float var = red[0] * (1.0f / V_DIM);
    float rstd = rsqrtf(var + 1e-12f);

    float4 g4 = ((const float4*)gamma)[tid];
    float4 b4 = ((const float4*)beta)[tid];
    float4 o4;
    o4.x = dx * rstd * g4.x + b4.x;
    o4.y = dy * rstd * g4.y + b4.y;
    o4.z = dz * rstd * g4.z + b4.z;
    o4.w = dw * rstd * g4.w + b4.w;
    ((float4*)(out + (size_t)t * V_DIM))[tid] = o4;
}

// ---------------- launch ---------------------------------------------------
extern "C" void kernel_launch(void* const* d_in, const int* in_sizes, int n_in,
                              void* d_out, int out_size)
{
    const float* hs     = (const float*)d_in[0];
    const float* inp    = (const float*)d_in[1];
    const float* Wd     = (const float*)d_in[2];
    const float* bd     = (const float*)d_in[3];
    const float* Wq     = (const float*)d_in[4];
    const float* bq     = (const float*)d_in[5];
    const float* keys   = (const float*)d_in[6];
    const float* values = (const float*)d_in[7];
    const float* gamma  = (const float*)d_in[8];
    const float* beta   = (const float*)d_in[9];
    float* out = (float*)d_out;

    void *p_C, *p_w, *p_i;
    cudaGetSymbolAddress(&p_C, g_C);
    cudaGetSymbolAddress(&p_w, g_w);
    cudaGetSymbolAddress(&p_i, g_i);
    float* C    = (float*)p_C;
    float* wbuf = (float*)p_w;
    int*   ibuf = (int*)p_i;

    cudaFuncSetAttribute(gemm_hmma, cudaFuncAttributeMaxDynamicSharedMemorySize, SMEM_TOTAL);
    cudaFuncSetAttribute(prep_misc, cudaFuncAttributeMaxDynamicSharedMemorySize, PREP_SMEM);

    // order: gemm_hmma is the 4th user kernel (ncu capture slot)
    split_trans<<<49152 + 2304, 256>>>(hs, Wd);
    prep_misc<<<197, 256, PREP_SMEM>>>(Wq, keys, bd, bq);
    cvt_values<<<(N_KEYS * N_KEYS * V_DIM / 4) / 256, 256>>>(values);
    gemm_hmma<<<dim3(NCAT / BN, T_TOT / BM), 256, SMEM_TOTAL>>>(C);
    pkm_topk<<<T_TOT * HEADS / 8, 256>>>(C, wbuf, ibuf);
    pkm_out<<<T_TOT, 192>>>(C, inp, wbuf, ibuf, gamma, beta, out);
}

// round 9
// speedup vs baseline: 6.9195x; 1.3509x over previous
#include <cuda_runtime.h>
#include <cuda_fp16.h>
#include <cuda_bf16.h>
#include <math.h>
#include <float.h>
#include <stdint.h>

#define T_TOT   16384
#define IN_DIM  3072
#define V_DIM   768
#define HEADS   4
#define KNN     32
#define N_KEYS  128
#define NCAT    1792            // 768 (dense) + 1024 (scores)
#define BM      256
#define BN      128
#define BK      64
#define STAGES  3
#define NCHUNK  48              // IN_DIM / BK, single fp16 pass
#define STAGE_BYTES (BM * BK * 2 + BN * BK * 2)   // 49152
#define SMEM_TOTAL  (STAGES * STAGE_BYTES)        // 147456
#define PREP_SMEM   (128 * 129 * 4 + 128 * 128 * 4)  // 131584

// ---------------- scratch (device globals; no allocation allowed) ----------
__device__ __align__(256) __half g_Ah[(size_t)T_TOT * IN_DIM];
__device__ __align__(256) __half g_Bh[(size_t)NCAT * IN_DIM];
__device__ __align__(256) float g_bias[NCAT];
__device__ __align__(256) float g_C[(size_t)T_TOT * NCAT];
__device__ __align__(256) float g_w[(size_t)T_TOT * HEADS * KNN];
__device__ __align__(256) int   g_i[(size_t)T_TOT * HEADS * KNN];
__device__ __align__(256) __nv_bfloat16 g_vb[(size_t)(N_KEYS * N_KEYS) * V_DIM];

// pruned product-key candidate table: (i<<5)|j for all (i+1)*(j+1) <= 32
__constant__ unsigned short c_tab[128] = {
    0,1,2,3,4,5,6,7,8,9,10,11,12,13,14,15,
    16,17,18,19,20,21,22,23,24,25,26,27,28,29,30,31,
    32,33,34,35,36,37,38,39,40,41,42,43,44,45,46,47,
    64,65,66,67,68,69,70,71,72,73,
    96,97,98,99,100,101,102,103,
    128,129,130,131,132,133,
    160,161,162,163,164,
    192,193,194,195,
    224,225,226,227,
    256,257,258,
    288,289,290,
    320,321, 352,353, 384,385, 416,417, 448,449, 480,481,
    512,544,576,608,640,672,704,736,768,800,832,864,896,928,960,992,
    0,0,0,0,0,0,0,0,0
};

// ---------------- PTX helpers ----------------------------------------------
__device__ __forceinline__ uint32_t smem_u32(const void* p) {
    uint32_t a;
    asm("{ .reg .u64 t; cvta.to.shared.u64 t, %1; cvt.u32.u64 %0, t; }" : "=r"(a) : "l"(p));
    return a;
}
#define SW128(off) ((off) ^ (((off) >> 3) & 0x70))

__device__ __forceinline__ void cp_async16(uint32_t dst, const void* src) {
    asm volatile("cp.async.cg.shared.global [%0], [%1], 16;" :: "r"(dst), "l"(src));
}
#define CP_COMMIT() asm volatile("cp.async.commit_group;" ::: "memory")
#define CP_WAIT1()  asm volatile("cp.async.wait_group 1;" ::: "memory")

#define LDSM4(r0, r1, r2, r3, addr) \
    asm volatile("ldmatrix.sync.aligned.m8n8.x4.shared.b16 {%0,%1,%2,%3}, [%4];" \
                 : "=r"(r0), "=r"(r1), "=r"(r2), "=r"(r3) : "r"(addr))

#define MMA16816(d, a0, a1, a2, a3, b0, b1) \
    asm volatile("mma.sync.aligned.m16n8k16.row.col.f32.f16.f16.f32 " \
                 "{%0,%1,%2,%3}, {%4,%5,%6,%7}, {%8,%9}, {%0,%1,%2,%3};" \
                 : "+f"((d)[0]), "+f"((d)[1]), "+f"((d)[2]), "+f"((d)[3]) \
                 : "r"(a0), "r"(a1), "r"(a2), "r"(a3), "r"(b0), "r"(b1))

// ---------------- prep: A -> fp16 + transpose W_dense -----------------------
__global__ __launch_bounds__(256) void split_trans(
    const float* __restrict__ X, const float* __restrict__ W)
{
    __shared__ float tile[32][33];
    const int b = blockIdx.x, t = threadIdx.x;
    if (b < 49152) {
        size_t i = (size_t)b * 256 + t;          // one float4
        float4 v = ((const float4*)X)[i];
        ushort4 h;
        h.x = __half_as_ushort(__float2half_rn(v.x));
        h.y = __half_as_ushort(__float2half_rn(v.y));
        h.z = __half_as_ushort(__float2half_rn(v.z));
        h.w = __half_as_ushort(__float2half_rn(v.w));
        ((ushort4*)g_Ah)[i] = h;
    } else {
        const int b2 = b - 49152;
        const int n0 = (b2 % 24) * 32, k0 = (b2 / 24) * 32;
        const int tx = t & 31, ty = t >> 5;
#pragma unroll
        for (int j = 0; j < 32; j += 8)
            tile[ty + j][tx] = W[(size_t)(k0 + ty + j) * V_DIM + n0 + tx];
        __syncthreads();
#pragma unroll
        for (int j = 0; j < 32; j += 8) {
            int n = n0 + ty + j, k = k0 + tx;
            g_Bh[(size_t)n * IN_DIM + k] = __float2half_rn(tile[tx][ty + j]);
        }
    }
}

// merged: W_keff = Wq x keys^T (rows 768..1791 of g_Bh), score bias, dense bias
__global__ __launch_bounds__(256) void prep_misc(
    const float* __restrict__ Wq, const float* __restrict__ keys,
    const float* __restrict__ bd, const float* __restrict__ bq)
{
    extern __shared__ float sm[];
    float (*Ws)[129] = (float(*)[129])sm;                 // [kloc][d]
    float (*Ks)[128] = (float(*)[128])(sm + 128 * 129);   // [n][d]
    const int b = blockIdx.x, t = threadIdx.x;

    if (b < 192) {
        const int hs = b & 7, kt = b >> 3;
        for (int i = t; i < 128 * 128; i += 256) {
            int r = i >> 7, d = i & 127;
            Ws[r][d] = Wq[(size_t)(kt * 128 + r) * 1024 + hs * 128 + d];
            Ks[r][d] = keys[(size_t)(hs * 128 + r) * 128 + d];
        }
        __syncthreads();
        const int kloc = t & 127, nh = t >> 7;
        for (int no = 0; no < 64; no++) {
            int n = nh * 64 + no;
            float acc = 0.f;
#pragma unroll 8
            for (int d = 0; d < 128; d++) acc += Ws[kloc][d] * Ks[n][d];
            g_Bh[(size_t)(V_DIM + hs * 128 + n) * IN_DIM + kt * 128 + kloc] =
                __float2half_rn(acc);
        }
    } else if (b < 196) {
        int np = (b - 192) * 256 + t;     // 0..1023
        int hs = np >> 7, n = np & 127;
        float acc = 0.f;
        for (int d = 0; d < 128; d++)
            acc += bq[hs * 128 + d] * keys[(size_t)(hs * 128 + n) * 128 + d];
        g_bias[V_DIM + np] = acc;
    } else {
        for (int i = t; i < V_DIM; i += 256) g_bias[i] = bd[i];
    }
}

// ---------------- values table -> bf16 --------------------------------------
__global__ __launch_bounds__(256) void cvt_values(const float* __restrict__ v)
{
    size_t i = (size_t)blockIdx.x * 256 + threadIdx.x;   // one float4
    float4 x = ((const float4*)v)[i];
    ushort4 o;
    o.x = __bfloat16_as_ushort(__float2bfloat16(x.x));
    o.y = __bfloat16_as_ushort(__float2bfloat16(x.y));
    o.z = __bfloat16_as_ushort(__float2bfloat16(x.z));
    o.w = __bfloat16_as_ushort(__float2bfloat16(x.w));
    ((ushort4*)g_vb)[i] = o;
}

// ---------------- HMMA GEMM: 256x128 CTA tile, 64x64 warp tile -------------
__device__ __forceinline__ void load_chunk(
    int chunk, int s, int tid, int bm, int bn, uint32_t sb)
{
    int k0 = chunk * BK;
    const __half* Ag = g_Ah + (size_t)(bm * BM) * IN_DIM + k0;
    const __half* Bg = g_Bh + (size_t)(bn * BN) * IN_DIM + k0;
    uint32_t sA = sb + s * STAGE_BYTES;
    uint32_t sB = sA + BM * BK * 2;
#pragma unroll
    for (int it = 0; it < 8; it++) {      // A: 2048 x 16B
        int u = tid + it * 256;
        int r = u >> 3, ch = u & 7;
        cp_async16(sA + SW128(r * 128 + ch * 16), Ag + (size_t)r * IN_DIM + ch * 8);
    }
#pragma unroll
    for (int it = 0; it < 4; it++) {      // B: 1024 x 16B
        int u = tid + it * 256;
        int r = u >> 3, ch = u & 7;
        cp_async16(sB + SW128(r * 128 + ch * 16), Bg + (size_t)r * IN_DIM + ch * 8);
    }
}

__global__ __launch_bounds__(256, 1) void gemm_hmma(float* __restrict__ C)
{
    extern __shared__ char smem[];
    uint32_t sb = smem_u32(smem);
    const int tid = threadIdx.x, wid = tid >> 5, lane = tid & 31;
    const int bn = blockIdx.x, bm = blockIdx.y;
    const int wm = wid & 3;          // M quarter: rows wm*64
    const int wn = wid >> 2;         // N half:   cols wn*64

    float acc[4][8][4];
#pragma unroll
    for (int a = 0; a < 4; a++)
#pragma unroll
        for (int b = 0; b < 8; b++)
#pragma unroll
            for (int c = 0; c < 4; c++) acc[a][b][c] = 0.f;

    const int sub = lane >> 3, lr = lane & 7;
    const int arow0 = wm * 64 + ((sub & 1) << 3) + lr;   // + mi*16
    const int akc = sub >> 1;
    const int brow0 = wn * 64 + ((sub >> 1) << 3) + lr;  // + nj*16
    const int bkc = sub & 1;

#pragma unroll
    for (int s = 0; s < STAGES - 1; s++) {
        load_chunk(s, s, tid, bm, bn, sb);
        CP_COMMIT();
    }

    int s = 0;
    for (int i = 0; i < NCHUNK; i++) {
        CP_WAIT1();
        __syncthreads();
        const int nc = i + STAGES - 1;
        if (nc < NCHUNK) {
            int sp = s + STAGES - 1; if (sp >= STAGES) sp -= STAGES;
            load_chunk(nc, sp, tid, bm, bn, sb);
        }
        CP_COMMIT();

        const uint32_t sA = sb + s * STAGE_BYTES;
        const uint32_t sB = sA + BM * BK * 2;
#pragma unroll
        for (int ks = 0; ks < 4; ks++) {
            uint32_t a[4][4];
#pragma unroll
            for (int mi = 0; mi < 4; mi++) {
                int row = arow0 + mi * 16;
                uint32_t ad = sA + row * 128 + (((2 * ks + akc) ^ (row & 7)) << 4);
                LDSM4(a[mi][0], a[mi][1], a[mi][2], a[mi][3], ad);
            }
            uint32_t b[4][4];
#pragma unroll
            for (int nj = 0; nj < 4; nj++) {
                int row = brow0 + nj * 16;
                uint32_t bd = sB + row * 128 + (((2 * ks + bkc) ^ (row & 7)) << 4);
                LDSM4(b[nj][0], b[nj][1], b[nj][2], b[nj][3], bd);
            }
#pragma unroll
            for (int mi = 0; mi < 4; mi++)
#pragma unroll
                for (int nj = 0; nj < 4; nj++) {
                    MMA16816(acc[mi][2 * nj],     a[mi][0], a[mi][1], a[mi][2], a[mi][3],
                             b[nj][0], b[nj][1]);
                    MMA16816(acc[mi][2 * nj + 1], a[mi][0], a[mi][1], a[mi][2], a[mi][3],
                             b[nj][2], b[nj][3]);
                }
        }
        if (++s == STAGES) s = 0;
    }

    const int mrow = bm * BM + wm * 64 + (lane >> 2);
    const int ncol = bn * BN + wn * 64 + 2 * (lane & 3);
#pragma unroll
    for (int nj = 0; nj < 8; nj++) {
        int c = ncol + nj * 8;
        float b0 = g_bias[c], b1 = g_bias[c + 1];
#pragma unroll
        for (int mi = 0; mi < 4; mi++) {
            int r0 = mrow + mi * 16;
            float2 v0 = make_float2(acc[mi][nj][0] + b0, acc[mi][nj][1] + b1);
            float2 v1 = make_float2(acc[mi][nj][2] + b0, acc[mi][nj][3] + b1);
            *(float2*)(C + (size_t)r0 * NCAT + c) = v0;
            *(float2*)(C + (size_t)(r0 + 8) * NCAT + c) = v1;
        }
    }
}

// ---------------- packed warp top-32-of-128 ---------------------------------
__device__ __forceinline__ uint32_t ordf(float f) {
    int b = __float_as_int(f);
    return (uint32_t)(b ^ ((b >> 31) | 0x80000000));
}
__device__ __forceinline__ float deordf(uint32_t u) {
    int b = (u & 0x80000000u) ? (int)(u ^ 0x80000000u) : ~(int)u;
    return __int_as_float(b);
}

#define PCEX(v, j, takeMax) do { \
    uint32_t _o = __shfl_xor_sync(0xffffffffu, (v), (j)); \
    (v) = (takeMax) ? ((v) > _o ? (v) : _o) : ((v) < _o ? (v) : _o); \
} while (0)

__device__ __forceinline__ uint32_t top32of128(uint32_t u[4], int lane)
{
#pragma unroll
    for (int k = 2; k <= 32; k <<= 1) {
#pragma unroll
        for (int j = k >> 1; j > 0; j >>= 1) {
            bool flag = (lane & k) == 0;
            bool lower = (lane & j) == 0;
            bool tm = (flag == lower);
#pragma unroll
            for (int r = 0; r < 4; r++) PCEX(u[r], j, tm);
        }
    }
    uint32_t a, b;
    {
        uint32_t o1 = __shfl_xor_sync(0xffffffffu, u[1], 31);
        uint32_t o3 = __shfl_xor_sync(0xffffffffu, u[3], 31);
        a = u[0] > o1 ? u[0] : o1;
        b = u[2] > o3 ? u[2] : o3;
    }
#pragma unroll
    for (int j = 16; j > 0; j >>= 1) {
        bool lower = (lane & j) == 0;
        PCEX(a, j, lower);
        PCEX(b, j, lower);
    }
    uint32_t m;
    {
        uint32_t ob = __shfl_xor_sync(0xffffffffu, b, 31);
        m = a > ob ? a : ob;
    }
#pragma unroll
    for (int j = 16; j > 0; j >>= 1) {
        bool lower = (lane & j) == 0;
        PCEX(m, j, lower);
    }
    return m;   // lane l = (l+1)-th largest
}

// ---------------- PKM top-k + softmax: one warp per (t,h) ------------------
__global__ __launch_bounds__(256) void pkm_topk(
    const float* __restrict__ Cmat,
    float* __restrict__ Wout, int* __restrict__ Iout)
{
    const int lane = threadIdx.x & 31;
    const int w = (blockIdx.x << 3) + (threadIdx.x >> 5);
    const int t = w >> 2, h = w & 3;
    const float* Srow = Cmat + (size_t)t * NCAT + V_DIM + h * 256;

    uint32_t u[4];
#pragma unroll
    for (int r = 0; r < 4; r++) {
        int e = r * 32 + lane;
        u[r] = (ordf(Srow[e]) & 0xFFFFFF80u) | (uint32_t)e;
    }
    uint32_t top1 = top32of128(u, lane);
#pragma unroll
    for (int r = 0; r < 4; r++) {
        int e = r * 32 + lane;
        u[r] = (ordf(Srow[128 + e]) & 0xFFFFFF80u) | (uint32_t)e;
    }
    uint32_t top2 = top32of128(u, lane);

#pragma unroll
    for (int r = 0; r < 4; r++) {
        int c = r * 32 + lane;
        int tab = c_tab[c];
        int i = tab >> 5, jj = tab & 31;
        uint32_t k1 = __shfl_sync(0xffffffffu, top1, i);
        uint32_t k2 = __shfl_sync(0xffffffffu, top2, jj);
        float f = deordf(k1 & 0xFFFFFF80u) + deordf(k2 & 0xFFFFFF80u);
        u[r] = (c < 119) ? ((ordf(f) & 0xFFFFFF80u) | (uint32_t)c)
                         : (uint32_t)c;
    }
    uint32_t m = top32of128(u, lane);

    int c = m & 127;
    int tab = c_tab[c];
    int i = tab >> 5, jj = tab & 31;
    uint32_t k1 = __shfl_sync(0xffffffffu, top1, i);
    uint32_t k2 = __shfl_sync(0xffffffffu, top2, jj);
    int idx = (int)(k1 & 127u) * N_KEYS + (int)(k2 & 127u);
    float val = deordf(m & 0xFFFFFF80u);
    float mx = __shfl_sync(0xffffffffu, val, 0);
    float e = expf(val - mx);
    float sum = e;
#pragma unroll
    for (int o = 16; o > 0; o >>= 1) sum += __shfl_xor_sync(0xffffffffu, sum, o);
    size_t base = (size_t)t * (HEADS * KNN) + h * KNN + lane;
    Wout[base] = e / sum;
    Iout[base] = idx;
}

// ---------------- gather (bf16 values) + residual + LayerNorm ---------------
__global__ __launch_bounds__(192) void pkm_out(
    const float* __restrict__ Cmat, const float* __restrict__ inp,
    const float* __restrict__ Wt, const int* __restrict__ It,
    const float* __restrict__ gamma, const float* __restrict__ beta,
    float* __restrict__ out)
{
    const int t = blockIdx.x;
    const int tid = threadIdx.x;

    __shared__ float wsh[HEADS * KNN];
    __shared__ int   ish[HEADS * KNN];
    __shared__ float red[192];

    if (tid < HEADS * KNN) {
        wsh[tid] = Wt[(size_t)t * (HEADS * KNN) + tid];
        ish[tid] = It[(size_t)t * (HEADS * KNN) + tid];
    }
    __syncthreads();

    float4 acc;
    {
        float4 d4 = ((const float4*)(Cmat + (size_t)t * NCAT))[tid];
        float4 r4 = ((const float4*)(inp  + (size_t)t * V_DIM))[tid];
        acc.x = d4.x + r4.x; acc.y = d4.y + r4.y;
        acc.z = d4.z + r4.z; acc.w = d4.w + r4.w;
    }

    float4 acc2 = make_float4(0.f, 0.f, 0.f, 0.f);
#pragma unroll 4
    for (int m = 0; m < HEADS * KNN; m += 2) {
        float w0 = wsh[m];
        ushort4 h0 = ((const ushort4*)(g_vb + (size_t)ish[m] * V_DIM))[tid];
        acc.x += w0 * __int_as_float((uint32_t)h0.x << 16);
        acc.y += w0 * __int_as_float((uint32_t)h0.y << 16);
        acc.z += w0 * __int_as_float((uint32_t)h0.z << 16);
        acc.w += w0 * __int_as_float((uint32_t)h0.w << 16);
        float w1 = wsh[m + 1];
        ushort4 h1 = ((const ushort4*)(g_vb + (size_t)ish[m + 1] * V_DIM))[tid];
        acc2.x += w1 * __int_as_float((uint32_t)h1.x << 16);
        acc2.y += w1 * __int_as_float((uint32_t)h1.y << 16);
        acc2.z += w1 * __int_as_float((uint32_t)h1.z << 16);
        acc2.w += w1 * __int_as_float((uint32_t)h1.w << 16);
    }
    acc.x += acc2.x; acc.y += acc2.y; acc.z += acc2.z; acc.w += acc2.w;

    red[tid] = acc.x + acc.y + acc.z + acc.w;
    __syncthreads();
    if (tid < 64) red[tid] += red[tid + 128];
    __syncthreads();
    if (tid < 64) red[tid] += red[tid + 64];
    __syncthreads();
    if (tid < 32) {
        float v = red[tid] + red[tid + 32];
#pragma unroll
        for (int o = 16; o > 0; o >>= 1) v += __shfl_xor_sync(0xffffffffu, v, o);
        if (tid == 0) red[0] = v;
    }
    __syncthreads();
    float mu = red[0] * (1.0f / V_DIM);
    __syncthreads();

    float dx = acc.x - mu, dy = acc.y - mu, dz = acc.z - mu, dw = acc.w - mu;
    red[tid] = dx * dx + dy * dy + dz * dz + dw * dw;
    __syncthreads();
    if (tid < 64) red[tid] += red[tid + 128];
    __syncthreads();
    if (tid < 64) red[tid] += red[tid + 64];
    __syncthreads();
    if (tid < 32) {
        float v = red[tid] + red[tid + 32];
#pragma unroll
        for (int o = 16; o > 0; o >>= 1) v += __shfl_xor_sync(0xffffffffu, v, o);
        if (tid == 0) red[0] = v;
    }
    __syncthreads();
    float var = red[0] * (1.0f / V_DIM);
    float rstd = rsqrtf(var + 1e-12f);

    float4 g4 = ((const float4*)gamma)[tid];
    float4 b4 = ((const float4*)beta)[tid];
    float4 o4;
    o4.x = dx * rstd * g4.x + b4.x;
    o4.y = dy * rstd * g4.y + b4.y;
    o4.z = dz * rstd * g4.z + b4.z;
    o4.w = dw * rstd * g4.w + b4.w;
    ((float4*)(out + (size_t)t * V_DIM))[tid] = o4;
}

// ---------------- launch ---------------------------------------------------
extern "C" void kernel_launch(void* const* d_in, const int* in_sizes, int n_in,
                              void* d_out, int out_size)
{
    const float* hs     = (const float*)d_in[0];
    const float* inp    = (const float*)d_in[1];
    const float* Wd     = (const float*)d_in[2];
    const float* bd     = (const float*)d_in[3];
    const float* Wq     = (const float*)d_in[4];
    const float* bq     = (const float*)d_in[5];
    const float* keys   = (const float*)d_in[6];
    const float* values = (const float*)d_in[7];
    const float* gamma  = (const float*)d_in[8];
    const float* beta   = (const float*)d_in[9];
    float* out = (float*)d_out;

    void *p_C, *p_w, *p_i;
    cudaGetSymbolAddress(&p_C, g_C);
    cudaGetSymbolAddress(&p_w, g_w);
    cudaGetSymbolAddress(&p_i, g_i);
    float* C    = (float*)p_C;
    float* wbuf = (float*)p_w;
    int*   ibuf = (int*)p_i;

    cudaFuncSetAttribute(gemm_hmma, cudaFuncAttributeMaxDynamicSharedMemorySize, SMEM_TOTAL);
    cudaFuncSetAttribute(prep_misc, cudaFuncAttributeMaxDynamicSharedMemorySize, PREP_SMEM);

    // order: gemm_hmma is the 4th user kernel (ncu capture slot)
    split_trans<<<49152 + 2304, 256>>>(hs, Wd);
    prep_misc<<<197, 256, PREP_SMEM>>>(Wq, keys, bd, bq);
    cvt_values<<<(N_KEYS * N_KEYS * V_DIM / 4) / 256, 256>>>(values);
    gemm_hmma<<<dim3(NCAT / BN, T_TOT / BM), 256, SMEM_TOTAL>>>(C);
    pkm_topk<<<T_TOT * HEADS / 8, 256>>>(C, wbuf, ibuf);
    pkm_out<<<T_TOT, 192>>>(C, inp, wbuf, ibuf, gamma, beta, out);
}

// round 11
// speedup vs baseline: 7.3948x; 1.0687x over previous
#include <cuda_runtime.h>
#include <cuda_fp16.h>
#include <cuda_bf16.h>
#include <math.h>
#include <float.h>
#include <stdint.h>

#define T_TOT   16384
#define IN_DIM  3072
#define V_DIM   768
#define HEADS   4
#define KNN     32
#define N_KEYS  128
#define NCAT    1792            // 768 (dense) + 1024 (scores)
#define BM      256
#define BN      128
#define BK      64
#define STAGES  4
#define NCHUNK  48              // IN_DIM / BK
#define STAGE_BYTES (BM * BK * 2 + BN * BK * 2)   // 49152
#define SMEM_TOTAL  (STAGES * STAGE_BYTES)        // 196608
#define PREP_SMEM   (128 * 129 * 4 + 128 * 128 * 4)  // 131584

// ---------------- scratch (device globals; no allocation allowed) ----------
__device__ __align__(256) __half g_Ah[(size_t)T_TOT * IN_DIM];
__device__ __align__(256) __half g_Bh[(size_t)NCAT * IN_DIM];
__device__ __align__(256) float g_bias[NCAT];
__device__ __align__(256) float g_C[(size_t)T_TOT * NCAT];
__device__ __align__(256) __nv_bfloat16 g_vb[(size_t)(N_KEYS * N_KEYS) * V_DIM];

// pruned product-key candidate table: (i<<5)|j for all (i+1)*(j+1) <= 32
__constant__ unsigned short c_tab[128] = {
    0,1,2,3,4,5,6,7,8,9,10,11,12,13,14,15,
    16,17,18,19,20,21,22,23,24,25,26,27,28,29,30,31,
    32,33,34,35,36,37,38,39,40,41,42,43,44,45,46,47,
    64,65,66,67,68,69,70,71,72,73,
    96,97,98,99,100,101,102,103,
    128,129,130,131,132,133,
    160,161,162,163,164,
    192,193,194,195,
    224,225,226,227,
    256,257,258,
    288,289,290,
    320,321, 352,353, 384,385, 416,417, 448,449, 480,481,
    512,544,576,608,640,672,704,736,768,800,832,864,896,928,960,992,
    0,0,0,0,0,0,0,0,0
};

// ---------------- PTX helpers ----------------------------------------------
__device__ __forceinline__ uint32_t smem_u32(const void* p) {
    uint32_t a;
    asm("{ .reg .u64 t; cvta.to.shared.u64 t, %1; cvt.u32.u64 %0, t; }" : "=r"(a) : "l"(p));
    return a;
}
#define SW128(off) ((off) ^ (((off) >> 3) & 0x70))

__device__ __forceinline__ void cp_async16(uint32_t dst, const void* src) {
    asm volatile("cp.async.cg.shared.global [%0], [%1], 16;" :: "r"(dst), "l"(src));
}
#define CP_COMMIT() asm volatile("cp.async.commit_group;" ::: "memory")
#define CP_WAIT2()  asm volatile("cp.async.wait_group 2;" ::: "memory")

#define LDSM4(r0, r1, r2, r3, addr) \
    asm volatile("ldmatrix.sync.aligned.m8n8.x4.shared.b16 {%0,%1,%2,%3}, [%4];" \
                 : "=r"(r0), "=r"(r1), "=r"(r2), "=r"(r3) : "r"(addr))

#define MMA16816(d, a0, a1, a2, a3, b0, b1) \
    asm volatile("mma.sync.aligned.m16n8k16.row.col.f32.f16.f16.f32 " \
                 "{%0,%1,%2,%3}, {%4,%5,%6,%7}, {%8,%9}, {%0,%1,%2,%3};" \
                 : "+f"((d)[0]), "+f"((d)[1]), "+f"((d)[2]), "+f"((d)[3]) \
                 : "r"(a0), "r"(a1), "r"(a2), "r"(a3), "r"(b0), "r"(b1))

// ---------------- prep: A -> fp16 + transpose W_dense -----------------------
__global__ __launch_bounds__(256) void split_trans(
    const float* __restrict__ X, const float* __restrict__ W)
{
    __shared__ float tile[32][33];
    const int b = blockIdx.x, t = threadIdx.x;
    if (b < 49152) {
        size_t i = (size_t)b * 256 + t;          // one float4
        float4 v = ((const float4*)X)[i];
        ushort4 h;
        h.x = __half_as_ushort(__float2half_rn(v.x));
        h.y = __half_as_ushort(__float2half_rn(v.y));
        h.z = __half_as_ushort(__float2half_rn(v.z));
        h.w = __half_as_ushort(__float2half_rn(v.w));
        ((ushort4*)g_Ah)[i] = h;
    } else {
        const int b2 = b - 49152;
        const int n0 = (b2 % 24) * 32, k0 = (b2 / 24) * 32;
        const int tx = t & 31, ty = t >> 5;
#pragma unroll
        for (int j = 0; j < 32; j += 8)
            tile[ty + j][tx] = W[(size_t)(k0 + ty + j) * V_DIM + n0 + tx];
        __syncthreads();
#pragma unroll
        for (int j = 0; j < 32; j += 8) {
            int n = n0 + ty + j, k = k0 + tx;
            g_Bh[(size_t)n * IN_DIM + k] = __float2half_rn(tile[tx][ty + j]);
        }
    }
}

// merged: W_keff = Wq x keys^T (rows 768..1791 of g_Bh), score bias, dense bias
__global__ __launch_bounds__(256) void prep_misc(
    const float* __restrict__ Wq, const float* __restrict__ keys,
    const float* __restrict__ bd, const float* __restrict__ bq)
{
    extern __shared__ float sm[];
    float (*Ws)[129] = (float(*)[129])sm;                 // [kloc][d]
    float (*Ks)[128] = (float(*)[128])(sm + 128 * 129);   // [n][d]
    const int b = blockIdx.x, t = threadIdx.x;

    if (b < 192) {
        const int hs = b & 7, kt = b >> 3;
        for (int i = t; i < 128 * 128; i += 256) {
            int r = i >> 7, d = i & 127;
            Ws[r][d] = Wq[(size_t)(kt * 128 + r) * 1024 + hs * 128 + d];
            Ks[r][d] = keys[(size_t)(hs * 128 + r) * 128 + d];
        }
        __syncthreads();
        const int kloc = t & 127, nh = t >> 7;
        for (int no = 0; no < 64; no++) {
            int n = nh * 64 + no;
            float acc = 0.f;
#pragma unroll 8
            for (int d = 0; d < 128; d++) acc += Ws[kloc][d] * Ks[n][d];
            g_Bh[(size_t)(V_DIM + hs * 128 + n) * IN_DIM + kt * 128 + kloc] =
                __float2half_rn(acc);
        }
    } else if (b < 196) {
        int np = (b - 192) * 256 + t;     // 0..1023
        int hs = np >> 7, n = np & 127;
        float acc = 0.f;
        for (int d = 0; d < 128; d++)
            acc += bq[hs * 128 + d] * keys[(size_t)(hs * 128 + n) * 128 + d];
        g_bias[V_DIM + np] = acc;
    } else {
        for (int i = t; i < V_DIM; i += 256) g_bias[i] = bd[i];
    }
}

// ---------------- values table -> bf16 --------------------------------------
__global__ __launch_bounds__(256) void cvt_values(const float* __restrict__ v)
{
    size_t i = (size_t)blockIdx.x * 256 + threadIdx.x;   // one float4
    float4 x = ((const float4*)v)[i];
    ushort4 o;
    o.x = __bfloat16_as_ushort(__float2bfloat16(x.x));
    o.y = __bfloat16_as_ushort(__float2bfloat16(x.y));
    o.z = __bfloat16_as_ushort(__float2bfloat16(x.z));
    o.w = __bfloat16_as_ushort(__float2bfloat16(x.w));
    ((ushort4*)g_vb)[i] = o;
}

// ---------------- HMMA GEMM: 256x128 CTA tile, 64x64 warp tile -------------
__device__ __forceinline__ void load_chunk(
    int chunk, int s, int tid, int bm, int bn, uint32_t sb)
{
    int k0 = chunk * BK;
    const __half* Ag = g_Ah + (size_t)(bm * BM) * IN_DIM + k0;
    const __half* Bg = g_Bh + (size_t)(bn * BN) * IN_DIM + k0;
    uint32_t sA = sb + s * STAGE_BYTES;
    uint32_t sB = sA + BM * BK * 2;
#pragma unroll
    for (int it = 0; it < 8; it++) {      // A: 2048 x 16B
        int u = tid + it * 256;
        int r = u >> 3, ch = u & 7;
        cp_async16(sA + SW128(r * 128 + ch * 16), Ag + (size_t)r * IN_DIM + ch * 8);
    }
#pragma unroll
    for (int it = 0; it < 4; it++) {      // B: 1024 x 16B
        int u = tid + it * 256;
        int r = u >> 3, ch = u & 7;
        cp_async16(sB + SW128(r * 128 + ch * 16), Bg + (size_t)r * IN_DIM + ch * 8);
    }
}

__global__ __launch_bounds__(256, 1) void gemm_hmma(float* __restrict__ C)
{
    extern __shared__ char smem[];
    uint32_t sb = smem_u32(smem);
    const int tid = threadIdx.x, wid = tid >> 5, lane = tid & 31;
    const int bn = blockIdx.x, bm = blockIdx.y;
    const int wm = wid & 3;          // M quarter: rows wm*64
    const int wn = wid >> 2;         // N half:   cols wn*64

    float acc[4][8][4];
#pragma unroll
    for (int a = 0; a < 4; a++)
#pragma unroll
        for (int b = 0; b < 8; b++)
#pragma unroll
            for (int c = 0; c < 4; c++) acc[a][b][c] = 0.f;

    const int sub = lane >> 3, lr = lane & 7;
    const int arow0 = wm * 64 + ((sub & 1) << 3) + lr;   // + mi*16
    const int akc = sub >> 1;
    const int brow0 = wn * 64 + ((sub >> 1) << 3) + lr;  // + nj*16
    const int bkc = sub & 1;

#pragma unroll
    for (int s = 0; s < STAGES - 1; s++) {
        load_chunk(s, s, tid, bm, bn, sb);
        CP_COMMIT();
    }

    for (int i = 0; i < NCHUNK; i++) {
        const int s = i & (STAGES - 1);
        CP_WAIT2();
        __syncthreads();
        const int nc = i + STAGES - 1;
        if (nc < NCHUNK) load_chunk(nc, nc & (STAGES - 1), tid, bm, bn, sb);
        CP_COMMIT();

        const uint32_t sA = sb + s * STAGE_BYTES;
        const uint32_t sB = sA + BM * BK * 2;
#pragma unroll
        for (int ks = 0; ks < 4; ks++) {
            uint32_t a[4][4];
#pragma unroll
            for (int mi = 0; mi < 4; mi++) {
                int row = arow0 + mi * 16;
                uint32_t ad = sA + row * 128 + (((2 * ks + akc) ^ (row & 7)) << 4);
                LDSM4(a[mi][0], a[mi][1], a[mi][2], a[mi][3], ad);
            }
            uint32_t b[4][4];
#pragma unroll
            for (int nj = 0; nj < 4; nj++) {
                int row = brow0 + nj * 16;
                uint32_t bd = sB + row * 128 + (((2 * ks + bkc) ^ (row & 7)) << 4);
                LDSM4(b[nj][0], b[nj][1], b[nj][2], b[nj][3], bd);
            }
#pragma unroll
            for (int mi = 0; mi < 4; mi++)
#pragma unroll
                for (int nj = 0; nj < 4; nj++) {
                    MMA16816(acc[mi][2 * nj],     a[mi][0], a[mi][1], a[mi][2], a[mi][3],
                             b[nj][0], b[nj][1]);
                    MMA16816(acc[mi][2 * nj + 1], a[mi][0], a[mi][1], a[mi][2], a[mi][3],
                             b[nj][2], b[nj][3]);
                }
        }
    }

    const int mrow = bm * BM + wm * 64 + (lane >> 2);
    const int ncol = bn * BN + wn * 64 + 2 * (lane & 3);
#pragma unroll
    for (int nj = 0; nj < 8; nj++) {
        int c = ncol + nj * 8;
        float b0 = g_bias[c], b1 = g_bias[c + 1];
#pragma unroll
        for (int mi = 0; mi < 4; mi++) {
            int r0 = mrow + mi * 16;
            float2 v0 = make_float2(acc[mi][nj][0] + b0, acc[mi][nj][1] + b1);
            float2 v1 = make_float2(acc[mi][nj][2] + b0, acc[mi][nj][3] + b1);
            *(float2*)(C + (size_t)r0 * NCAT + c) = v0;
            *(float2*)(C + (size_t)(r0 + 8) * NCAT + c) = v1;
        }
    }
}

// ---------------- packed warp top-32-of-128 ---------------------------------
__device__ __forceinline__ uint32_t ordf(float f) {
    int b = __float_as_int(f);
    return (uint32_t)(b ^ ((b >> 31) | 0x80000000));
}
__device__ __forceinline__ float deordf(uint32_t u) {
    int b = (u & 0x80000000u) ? (int)(u ^ 0x80000000u) : ~(int)u;
    return __int_as_float(b);
}

#define PCEX(v, j, takeMax) do { \
    uint32_t _o = __shfl_xor_sync(0xffffffffu, (v), (j)); \
    (v) = (takeMax) ? ((v) > _o ? (v) : _o) : ((v) < _o ? (v) : _o); \
} while (0)

__device__ __forceinline__ uint32_t top32of128(uint32_t u[4], int lane)
{
#pragma unroll
    for (int k = 2; k <= 32; k <<= 1) {
#pragma unroll
        for (int j = k >> 1; j > 0; j >>= 1) {
            bool flag = (lane & k) == 0;
            bool lower = (lane & j) == 0;
            bool tm = (flag == lower);
#pragma unroll
            for (int r = 0; r < 4; r++) PCEX(u[r], j, tm);
        }
    }
    uint32_t a, b;
    {
        uint32_t o1 = __shfl_xor_sync(0xffffffffu, u[1], 31);
        uint32_t o3 = __shfl_xor_sync(0xffffffffu, u[3], 31);
        a = u[0] > o1 ? u[0] : o1;
        b = u[2] > o3 ? u[2] : o3;
    }
#pragma unroll
    for (int j = 16; j > 0; j >>= 1) {
        bool lower = (lane & j) == 0;
        PCEX(a, j, lower);
        PCEX(b, j, lower);
    }
    uint32_t m;
    {
        uint32_t ob = __shfl_xor_sync(0xffffffffu, b, 31);
        m = a > ob ? a : ob;
    }
#pragma unroll
    for (int j = 16; j > 0; j >>= 1) {
        bool lower = (lane & j) == 0;
        PCEX(m, j, lower);
    }
    return m;   // lane l = (l+1)-th largest
}

// ---------------- fused: top-k + softmax + gather + residual + LayerNorm ----
// one block per token, 192 threads; warps 0-3 do top-k for heads 0-3
__global__ __launch_bounds__(192) void pkm_fused(
    const float* __restrict__ Cmat, const float* __restrict__ inp,
    const float* __restrict__ gamma, const float* __restrict__ beta,
    float* __restrict__ out)
{
    const int t = blockIdx.x;
    const int tid = threadIdx.x;
    const int wid = tid >> 5, lane = tid & 31;

    __shared__ float wsh[HEADS * KNN];
    __shared__ int   ish[HEADS * KNN];
    __shared__ float red[192];

    // ---- phase 1: per-head top-32 + softmax (warps 0-3) ----
    if (wid < HEADS) {
        const int h = wid;
        const float* Srow = Cmat + (size_t)t * NCAT + V_DIM + h * 256;

        uint32_t u[4];
#pragma unroll
        for (int r = 0; r < 4; r++) {
            int e = r * 32 + lane;
            u[r] = (ordf(Srow[e]) & 0xFFFFFF80u) | (uint32_t)e;
        }
        uint32_t top1 = top32of128(u, lane);
#pragma unroll
        for (int r = 0; r < 4; r++) {
            int e = r * 32 + lane;
            u[r] = (ordf(Srow[128 + e]) & 0xFFFFFF80u) | (uint32_t)e;
        }
        uint32_t top2 = top32of128(u, lane);

#pragma unroll
        for (int r = 0; r < 4; r++) {
            int c = r * 32 + lane;
            int tab = c_tab[c];
            int i = tab >> 5, jj = tab & 31;
            uint32_t k1 = __shfl_sync(0xffffffffu, top1, i);
            uint32_t k2 = __shfl_sync(0xffffffffu, top2, jj);
            float f = deordf(k1 & 0xFFFFFF80u) + deordf(k2 & 0xFFFFFF80u);
            u[r] = (c < 119) ? ((ordf(f) & 0xFFFFFF80u) | (uint32_t)c)
                             : (uint32_t)c;
        }
        uint32_t m = top32of128(u, lane);

        int c = m & 127;
        int tab = c_tab[c];
        int i = tab >> 5, jj = tab & 31;
        uint32_t k1 = __shfl_sync(0xffffffffu, top1, i);
        uint32_t k2 = __shfl_sync(0xffffffffu, top2, jj);
        int idx = (int)(k1 & 127u) * N_KEYS + (int)(k2 & 127u);
        float val = deordf(m & 0xFFFFFF80u);
        float mx = __shfl_sync(0xffffffffu, val, 0);
        float e = expf(val - mx);
        float sum = e;
#pragma unroll
        for (int o = 16; o > 0; o >>= 1) sum += __shfl_xor_sync(0xffffffffu, sum, o);
        wsh[h * KNN + lane] = e / sum;
        ish[h * KNN + lane] = idx;
    }
    __syncthreads();

    // ---- phase 2: gather + residual + LN (all 192 threads) ----
    float4 acc;
    {
        float4 d4 = ((const float4*)(Cmat + (size_t)t * NCAT))[tid];
        float4 r4 = ((const float4*)(inp  + (size_t)t * V_DIM))[tid];
        acc.x = d4.x + r4.x; acc.y = d4.y + r4.y;
        acc.z = d4.z + r4.z; acc.w = d4.w + r4.w;
    }

    float4 acc2 = make_float4(0.f, 0.f, 0.f, 0.f);
#pragma unroll 4
    for (int m = 0; m < HEADS * KNN; m += 2) {
        float w0 = wsh[m];
        ushort4 h0 = ((const ushort4*)(g_vb + (size_t)ish[m] * V_DIM))[tid];
        acc.x += w0 * __int_as_float((uint32_t)h0.x << 16);
        acc.y += w0 * __int_as_float((uint32_t)h0.y << 16);
        acc.z += w0 * __int_as_float((uint32_t)h0.z << 16);
        acc.w += w0 * __int_as_float((uint32_t)h0.w << 16);
        float w1 = wsh[m + 1];
        ushort4 h1 = ((const ushort4*)(g_vb + (size_t)ish[m + 1] * V_DIM))[tid];
        acc2.x += w1 * __int_as_float((uint32_t)h1.x << 16);
        acc2.y += w1 * __int_as_float((uint32_t)h1.y << 16);
        acc2.z += w1 * __int_as_float((uint32_t)h1.z << 16);
        acc2.w += w1 * __int_as_float((uint32_t)h1.w << 16);
    }
    acc.x += acc2.x; acc.y += acc2.y; acc.z += acc2.z; acc.w += acc2.w;

    red[tid] = acc.x + acc.y + acc.z + acc.w;
    __syncthreads();
    if (tid < 64) red[tid] += red[tid + 128];
    __syncthreads();
    if (tid < 64) red[tid] += red[tid + 64];
    __syncthreads();
    if (tid < 32) {
        float v = red[tid] + red[tid + 32];
#pragma unroll
        for (int o = 16; o > 0; o >>= 1) v += __shfl_xor_sync(0xffffffffu, v, o);
        if (tid == 0) red[0] = v;
    }
    __syncthreads();
    float mu = red[0] * (1.0f / V_DIM);
    __syncthreads();

    float dx = acc.x - mu, dy = acc.y - mu, dz = acc.z - mu, dw = acc.w - mu;
    red[tid] = dx * dx + dy * dy + dz * dz + dw * dw;
    __syncthreads();
    if (tid < 64) red[tid] += red[tid + 128];
    __syncthreads();
    if (tid < 64) red[tid] += red[tid + 64];
    __syncthreads();
    if (tid < 32) {
        float v = red[tid] + red[tid + 32];
#pragma unroll
        for (int o = 16; o > 0; o >>= 1) v += __shfl_xor_sync(0xffffffffu, v, o);
        if (tid == 0) red[0] = v;
    }
    __syncthreads();
    float var = red[0] * (1.0f / V_DIM);
    float rstd = rsqrtf(var + 1e-12f);

    float4 g4 = ((const float4*)gamma)[tid];
    float4 b4 = ((const float4*)beta)[tid];
    float4 o4;
    o4.x = dx * rstd * g4.x + b4.x;
    o4.y = dy * rstd * g4.y + b4.y;
    o4.z = dz * rstd * g4.z + b4.z;
    o4.w = dw * rstd * g4.w + b4.w;
    ((float4*)(out + (size_t)t * V_DIM))[tid] = o4;
}

// ---------------- launch ---------------------------------------------------
extern "C" void kernel_launch(void* const* d_in, const int* in_sizes, int n_in,
                              void* d_out, int out_size)
{
    const float* hs     = (const float*)d_in[0];
    const float* inp    = (const float*)d_in[1];
    const float* Wd     = (const float*)d_in[2];
    const float* bd     = (const float*)d_in[3];
    const float* Wq     = (const float*)d_in[4];
    const float* bq     = (const float*)d_in[5];
    const float* keys   = (const float*)d_in[6];
    const float* values = (const float*)d_in[7];
    const float* gamma  = (const float*)d_in[8];
    const float* beta   = (const float*)d_in[9];
    float* out = (float*)d_out;

    void* p_C;
    cudaGetSymbolAddress(&p_C, g_C);
    float* C = (float*)p_C;

    cudaFuncSetAttribute(gemm_hmma, cudaFuncAttributeMaxDynamicSharedMemorySize, SMEM_TOTAL);
    cudaFuncSetAttribute(prep_misc, cudaFuncAttributeMaxDynamicSharedMemorySize, PREP_SMEM);

    // order: gemm_hmma is the 4th user kernel (ncu capture slot)
    split_trans<<<49152 + 2304, 256>>>(hs, Wd);
    prep_misc<<<197, 256, PREP_SMEM>>>(Wq, keys, bd, bq);
    cvt_values<<<(N_KEYS * N_KEYS * V_DIM / 4) / 256, 256>>>(values);
    gemm_hmma<<<dim3(NCAT / BN, T_TOT / BM), 256, SMEM_TOTAL>>>(C);
    pkm_fused<<<T_TOT, 192>>>(C, inp, gamma, beta, out);
}

// round 13
// speedup vs baseline: 7.9400x; 1.0737x over previous
#include <cuda_runtime.h>
#include <cuda_fp16.h>
#include <cuda_bf16.h>
#include <math.h>
#include <float.h>
#include <stdint.h>

#define T_TOT   16384
#define IN_DIM  3072
#define V_DIM   768
#define HEADS   4
#define KNN     32
#define N_KEYS  128
#define NCAT    1792            // 768 (dense) + 1024 (scores)
#define BM      128
#define BN      128
#define BK      64
#define STAGES  3
#define NCHUNK  48              // IN_DIM / BK
#define STAGE_BYTES (BM * BK * 2 + BN * BK * 2)   // 32768
#define SMEM_TOTAL  (STAGES * STAGE_BYTES)        // 98304
#define PREP_SMEM   (128 * 129 * 4 + 128 * 128 * 4)  // 131584

// ---------------- scratch (device globals; no allocation allowed) ----------
__device__ __align__(256) __half g_Ah[(size_t)T_TOT * IN_DIM];
__device__ __align__(256) __half g_Bh[(size_t)NCAT * IN_DIM];
__device__ __align__(256) float g_bias[NCAT];
__device__ __align__(256) float g_C[(size_t)T_TOT * NCAT];
__device__ __align__(256) __nv_bfloat16 g_vb[(size_t)(N_KEYS * N_KEYS) * V_DIM];

// pruned product-key candidate table: (i<<5)|j for all (i+1)*(j+1) <= 32
__constant__ unsigned short c_tab[128] = {
    0,1,2,3,4,5,6,7,8,9,10,11,12,13,14,15,
    16,17,18,19,20,21,22,23,24,25,26,27,28,29,30,31,
    32,33,34,35,36,37,38,39,40,41,42,43,44,45,46,47,
    64,65,66,67,68,69,70,71,72,73,
    96,97,98,99,100,101,102,103,
    128,129,130,131,132,133,
    160,161,162,163,164,
    192,193,194,195,
    224,225,226,227,
    256,257,258,
    288,289,290,
    320,321, 352,353, 384,385, 416,417, 448,449, 480,481,
    512,544,576,608,640,672,704,736,768,800,832,864,896,928,960,992,
    0,0,0,0,0,0,0,0,0
};

// ---------------- PTX helpers ----------------------------------------------
__device__ __forceinline__ uint32_t smem_u32(const void* p) {
    uint32_t a;
    asm("{ .reg .u64 t; cvta.to.shared.u64 t, %1; cvt.u32.u64 %0, t; }" : "=r"(a) : "l"(p));
    return a;
}
#define SW128(off) ((off) ^ (((off) >> 3) & 0x70))

__device__ __forceinline__ void cp_async16(uint32_t dst, const void* src) {
    asm volatile("cp.async.cg.shared.global [%0], [%1], 16;" :: "r"(dst), "l"(src));
}
#define CP_COMMIT() asm volatile("cp.async.commit_group;" ::: "memory")
#define CP_WAIT1()  asm volatile("cp.async.wait_group 1;" ::: "memory")

#define LDSM4(r0, r1, r2, r3, addr) \
    asm volatile("ldmatrix.sync.aligned.m8n8.x4.shared.b16 {%0,%1,%2,%3}, [%4];" \
                 : "=r"(r0), "=r"(r1), "=r"(r2), "=r"(r3) : "r"(addr))

#define MMA16816(d, a0, a1, a2, a3, b0, b1) \
    asm volatile("mma.sync.aligned.m16n8k16.row.col.f32.f16.f16.f32 " \
                 "{%0,%1,%2,%3}, {%4,%5,%6,%7}, {%8,%9}, {%0,%1,%2,%3};" \
                 : "+f"((d)[0]), "+f"((d)[1]), "+f"((d)[2]), "+f"((d)[3]) \
                 : "r"(a0), "r"(a1), "r"(a2), "r"(a3), "r"(b0), "r"(b1))

// ---------------- prep: A -> fp16 + transpose W_dense -----------------------
__global__ __launch_bounds__(256) void split_trans(
    const float* __restrict__ X, const float* __restrict__ W)
{
    __shared__ float tile[32][33];
    const int b = blockIdx.x, t = threadIdx.x;
    if (b < 49152) {
        size_t i = (size_t)b * 256 + t;          // one float4
        float4 v = ((const float4*)X)[i];
        ushort4 h;
        h.x = __half_as_ushort(__float2half_rn(v.x));
        h.y = __half_as_ushort(__float2half_rn(v.y));
        h.z = __half_as_ushort(__float2half_rn(v.z));
        h.w = __half_as_ushort(__float2half_rn(v.w));
        ((ushort4*)g_Ah)[i] = h;
    } else {
        const int b2 = b - 49152;
        const int n0 = (b2 % 24) * 32, k0 = (b2 / 24) * 32;
        const int tx = t & 31, ty = t >> 5;
#pragma unroll
        for (int j = 0; j < 32; j += 8)
            tile[ty + j][tx] = W[(size_t)(k0 + ty + j) * V_DIM + n0 + tx];
        __syncthreads();
#pragma unroll
        for (int j = 0; j < 32; j += 8) {
            int n = n0 + ty + j, k = k0 + tx;
            g_Bh[(size_t)n * IN_DIM + k] = __float2half_rn(tile[tx][ty + j]);
        }
    }
}

// merged: W_keff = Wq x keys^T (rows 768..1791 of g_Bh), score bias, dense bias
__global__ __launch_bounds__(256) void prep_misc(
    const float* __restrict__ Wq, const float* __restrict__ keys,
    const float* __restrict__ bd, const float* __restrict__ bq)
{
    extern __shared__ float sm[];
    float (*Ws)[129] = (float(*)[129])sm;                 // [kloc][d]
    float (*Ks)[128] = (float(*)[128])(sm + 128 * 129);   // [n][d]
    const int b = blockIdx.x, t = threadIdx.x;

    if (b < 192) {
        const int hs = b & 7, kt = b >> 3;
        for (int i = t; i < 128 * 128; i += 256) {
            int r = i >> 7, d = i & 127;
            Ws[r][d] = Wq[(size_t)(kt * 128 + r) * 1024 + hs * 128 + d];
            Ks[r][d] = keys[(size_t)(hs * 128 + r) * 128 + d];
        }
        __syncthreads();
        const int kloc = t & 127, nh = t >> 7;
        for (int no = 0; no < 64; no++) {
            int n = nh * 64 + no;
            float acc = 0.f;
#pragma unroll 8
            for (int d = 0; d < 128; d++) acc += Ws[kloc][d] * Ks[n][d];
            g_Bh[(size_t)(V_DIM + hs * 128 + n) * IN_DIM + kt * 128 + kloc] =
                __float2half_rn(acc);
        }
    } else if (b < 196) {
        int np = (b - 192) * 256 + t;     // 0..1023
        int hs = np >> 7, n = np & 127;
        float acc = 0.f;
        for (int d = 0; d < 128; d++)
            acc += bq[hs * 128 + d] * keys[(size_t)(hs * 128 + n) * 128 + d];
        g_bias[V_DIM + np] = acc;
    } else {
        for (int i = t; i < V_DIM; i += 256) g_bias[i] = bd[i];
    }
}

// ---------------- values table -> bf16 --------------------------------------
__global__ __launch_bounds__(256) void cvt_values(const float* __restrict__ v)
{
    size_t i = (size_t)blockIdx.x * 256 + threadIdx.x;   // one float4
    float4 x = ((const float4*)v)[i];
    ushort4 o;
    o.x = __bfloat16_as_ushort(__float2bfloat16(x.x));
    o.y = __bfloat16_as_ushort(__float2bfloat16(x.y));
    o.z = __bfloat16_as_ushort(__float2bfloat16(x.z));
    o.w = __bfloat16_as_ushort(__float2bfloat16(x.w));
    ((ushort4*)g_vb)[i] = o;
}

// ---------------- HMMA GEMM: 128x128 CTA tile, 64x64 warp tile, 2 CTA/SM ---
__device__ __forceinline__ void load_chunk(
    int chunk, int s, int tid, int bm, int bn, uint32_t sb)
{
    int k0 = chunk * BK;
    const __half* Ag = g_Ah + (size_t)(bm * BM) * IN_DIM + k0;
    const __half* Bg = g_Bh + (size_t)(bn * BN) * IN_DIM + k0;
    uint32_t sA = sb + s * STAGE_BYTES;
    uint32_t sB = sA + BM * BK * 2;
#pragma unroll
    for (int it = 0; it < 8; it++) {      // A: 1024 x 16B over 128 threads
        int u = tid + it * 128;
        int r = u >> 3, ch = u & 7;
        cp_async16(sA + SW128(r * 128 + ch * 16), Ag + (size_t)r * IN_DIM + ch * 8);
    }
#pragma unroll
    for (int it = 0; it < 8; it++) {      // B: 1024 x 16B
        int u = tid + it * 128;
        int r = u >> 3, ch = u & 7;
        cp_async16(sB + SW128(r * 128 + ch * 16), Bg + (size_t)r * IN_DIM + ch * 8);
    }
}

__global__ __launch_bounds__(128, 2) void gemm_hmma(float* __restrict__ C)
{
    extern __shared__ char smem[];
    uint32_t sb = smem_u32(smem);
    const int tid = threadIdx.x, wid = tid >> 5, lane = tid & 31;
    const int bn = blockIdx.x, bm = blockIdx.y;
    const int wm = wid & 1;          // M half: rows wm*64
    const int wn = wid >> 1;         // N half: cols wn*64

    float acc[4][8][4];
#pragma unroll
    for (int a = 0; a < 4; a++)
#pragma unroll
        for (int b = 0; b < 8; b++)
#pragma unroll
            for (int c = 0; c < 4; c++) acc[a][b][c] = 0.f;

    const int sub = lane >> 3, lr = lane & 7;
    const int arow0 = wm * 64 + ((sub & 1) << 3) + lr;   // + mi*16
    const int akc = sub >> 1;
    const int brow0 = wn * 64 + ((sub >> 1) << 3) + lr;  // + nj*16
    const int bkc = sub & 1;

#pragma unroll
    for (int s = 0; s < STAGES - 1; s++) {
        load_chunk(s, s, tid, bm, bn, sb);
        CP_COMMIT();
    }

    int s = 0;
    for (int i = 0; i < NCHUNK; i++) {
        CP_WAIT1();
        __syncthreads();
        const int nc = i + STAGES - 1;
        if (nc < NCHUNK) {
            int sp = s + STAGES - 1; if (sp >= STAGES) sp -= STAGES;
            load_chunk(nc, sp, tid, bm, bn, sb);
        }
        CP_COMMIT();

        const uint32_t sA = sb + s * STAGE_BYTES;
        const uint32_t sB = sA + BM * BK * 2;
#pragma unroll
        for (int ks = 0; ks < 4; ks++) {
            uint32_t a[4][4];
#pragma unroll
            for (int mi = 0; mi < 4; mi++) {
                int row = arow0 + mi * 16;
                uint32_t ad = sA + row * 128 + (((2 * ks + akc) ^ (row & 7)) << 4);
                LDSM4(a[mi][0], a[mi][1], a[mi][2], a[mi][3], ad);
            }
            uint32_t b[4][4];
#pragma unroll
            for (int nj = 0; nj < 4; nj++) {
                int row = brow0 + nj * 16;
                uint32_t bd = sB + row * 128 + (((2 * ks + bkc) ^ (row & 7)) << 4);
                LDSM4(b[nj][0], b[nj][1], b[nj][2], b[nj][3], bd);
            }
#pragma unroll
            for (int mi = 0; mi < 4; mi++)
#pragma unroll
                for (int nj = 0; nj < 4; nj++) {
                    MMA16816(acc[mi][2 * nj],     a[mi][0], a[mi][1], a[mi][2], a[mi][3],
                             b[nj][0], b[nj][1]);
                    MMA16816(acc[mi][2 * nj + 1], a[mi][0], a[mi][1], a[mi][2], a[mi][3],
                             b[nj][2], b[nj][3]);
                }
        }
        if (++s == STAGES) s = 0;
    }

    const int mrow = bm * BM + wm * 64 + (lane >> 2);
    const int ncol = bn * BN + wn * 64 + 2 * (lane & 3);
#pragma unroll
    for (int nj = 0; nj < 8; nj++) {
        int c = ncol + nj * 8;
        float b0 = g_bias[c], b1 = g_bias[c + 1];
#pragma unroll
        for (int mi = 0; mi < 4; mi++) {
            int r0 = mrow + mi * 16;
            float2 v0 = make_float2(acc[mi][nj][0] + b0, acc[mi][nj][1] + b1);
            float2 v1 = make_float2(acc[mi][nj][2] + b0, acc[mi][nj][3] + b1);
            *(float2*)(C + (size_t)r0 * NCAT + c) = v0;
            *(float2*)(C + (size_t)(r0 + 8) * NCAT + c) = v1;
        }
    }
}

// ---------------- packed warp top-32-of-128 ---------------------------------
__device__ __forceinline__ uint32_t ordf(float f) {
    int b = __float_as_int(f);
    return (uint32_t)(b ^ ((b >> 31) | 0x80000000));
}
__device__ __forceinline__ float deordf(uint32_t u) {
    int b = (u & 0x80000000u) ? (int)(u ^ 0x80000000u) : ~(int)u;
    return __int_as_float(b);
}

#define PCEX(v, j, takeMax) do { \
    uint32_t _o = __shfl_xor_sync(0xffffffffu, (v), (j)); \
    (v) = (takeMax) ? ((v) > _o ? (v) : _o) : ((v) < _o ? (v) : _o); \
} while (0)

__device__ __forceinline__ uint32_t top32of128(uint32_t u[4], int lane)
{
#pragma unroll
    for (int k = 2; k <= 32; k <<= 1) {
#pragma unroll
        for (int j = k >> 1; j > 0; j >>= 1) {
            bool flag = (lane & k) == 0;
            bool lower = (lane & j) == 0;
            bool tm = (flag == lower);
#pragma unroll
            for (int r = 0; r < 4; r++) PCEX(u[r], j, tm);
        }
    }
    uint32_t a, b;
    {
        uint32_t o1 = __shfl_xor_sync(0xffffffffu, u[1], 31);
        uint32_t o3 = __shfl_xor_sync(0xffffffffu, u[3], 31);
        a = u[0] > o1 ? u[0] : o1;
        b = u[2] > o3 ? u[2] : o3;
    }
#pragma unroll
    for (int j = 16; j > 0; j >>= 1) {
        bool lower = (lane & j) == 0;
        PCEX(a, j, lower);
        PCEX(b, j, lower);
    }
    uint32_t m;
    {
        uint32_t ob = __shfl_xor_sync(0xffffffffu, b, 31);
        m = a > ob ? a : ob;
    }
#pragma unroll
    for (int j = 16; j > 0; j >>= 1) {
        bool lower = (lane & j) == 0;
        PCEX(m, j, lower);
    }
    return m;   // lane l = (l+1)-th largest
}

// ---------------- fused: top-k + softmax + gather + residual + LayerNorm ----
__global__ __launch_bounds__(192) void pkm_fused(
    const float* __restrict__ Cmat, const float* __restrict__ inp,
    const float* __restrict__ gamma, const float* __restrict__ beta,
    float* __restrict__ out)
{
    const int t = blockIdx.x;
    const int tid = threadIdx.x;
    const int wid = tid >> 5, lane = tid & 31;

    __shared__ float wsh[HEADS * KNN];
    __shared__ int   ish[HEADS * KNN];
    __shared__ float red[192];

    // ---- phase 1: per-head top-32 + softmax (warps 0-3) ----
    if (wid < HEADS) {
        const int h = wid;
        const float* Srow = Cmat + (size_t)t * NCAT + V_DIM + h * 256;

        uint32_t u[4];
#pragma unroll
        for (int r = 0; r < 4; r++) {
            int e = r * 32 + lane;
            u[r] = (ordf(Srow[e]) & 0xFFFFFF80u) | (uint32_t)e;
        }
        uint32_t top1 = top32of128(u, lane);
#pragma unroll
        for (int r = 0; r < 4; r++) {
            int e = r * 32 + lane;
            u[r] = (ordf(Srow[128 + e]) & 0xFFFFFF80u) | (uint32_t)e;
        }
        uint32_t top2 = top32of128(u, lane);

#pragma unroll
        for (int r = 0; r < 4; r++) {
            int c = r * 32 + lane;
            int tab = c_tab[c];
            int i = tab >> 5, jj = tab & 31;
            uint32_t k1 = __shfl_sync(0xffffffffu, top1, i);
            uint32_t k2 = __shfl_sync(0xffffffffu, top2, jj);
            float f = deordf(k1 & 0xFFFFFF80u) + deordf(k2 & 0xFFFFFF80u);
            u[r] = (c < 119) ? ((ordf(f) & 0xFFFFFF80u) | (uint32_t)c)
                             : (uint32_t)c;
        }
        uint32_t m = top32of128(u, lane);

        int c = m & 127;
        int tab = c_tab[c];
        int i = tab >> 5, jj = tab & 31;
        uint32_t k1 = __shfl_sync(0xffffffffu, top1, i);
        uint32_t k2 = __shfl_sync(0xffffffffu, top2, jj);
        int idx = (int)(k1 & 127u) * N_KEYS + (int)(k2 & 127u);
        float val = deordf(m & 0xFFFFFF80u);
        float mx = __shfl_sync(0xffffffffu, val, 0);
        float e = expf(val - mx);
        float sum = e;
#pragma unroll
        for (int o = 16; o > 0; o >>= 1) sum += __shfl_xor_sync(0xffffffffu, sum, o);
        wsh[h * KNN + lane] = e / sum;
        ish[h * KNN + lane] = idx;
    }
    __syncthreads();

    // ---- phase 2: gather + residual + LN (all 192 threads) ----
    float4 acc;
    {
        float4 d4 = ((const float4*)(Cmat + (size_t)t * NCAT))[tid];
        float4 r4 = ((const float4*)(inp  + (size_t)t * V_DIM))[tid];
        acc.x = d4.x + r4.x; acc.y = d4.y + r4.y;
        acc.z = d4.z + r4.z; acc.w = d4.w + r4.w;
    }

    float4 acc2 = make_float4(0.f, 0.f, 0.f, 0.f);
#pragma unroll 4
    for (int m = 0; m < HEADS * KNN; m += 2) {
        float w0 = wsh[m];
        ushort4 h0 = ((const ushort4*)(g_vb + (size_t)ish[m] * V_DIM))[tid];
        acc.x += w0 * __int_as_float((uint32_t)h0.x << 16);
        acc.y += w0 * __int_as_float((uint32_t)h0.y << 16);
        acc.z += w0 * __int_as_float((uint32_t)h0.z << 16);
        acc.w += w0 * __int_as_float((uint32_t)h0.w << 16);
        float w1 = wsh[m + 1];
        ushort4 h1 = ((const ushort4*)(g_vb + (size_t)ish[m + 1] * V_DIM))[tid];
        acc2.x += w1 * __int_as_float((uint32_t)h1.x << 16);
        acc2.y += w1 * __int_as_float((uint32_t)h1.y << 16);
        acc2.z += w1 * __int_as_float((uint32_t)h1.z << 16);
        acc2.w += w1 * __int_as_float((uint32_t)h1.w << 16);
    }
    acc.x += acc2.x; acc.y += acc2.y; acc.z += acc2.z; acc.w += acc2.w;

    red[tid] = acc.x + acc.y + acc.z + acc.w;
    __syncthreads();
    if (tid < 64) red[tid] += red[tid + 128];
    __syncthreads();
    if (tid < 64) red[tid] += red[tid + 64];
    __syncthreads();
    if (tid < 32) {
        float v = red[tid] + red[tid + 32];
#pragma unroll
        for (int o = 16; o > 0; o >>= 1) v += __shfl_xor_sync(0xffffffffu, v, o);
        if (tid == 0) red[0] = v;
    }
    __syncthreads();
    float mu = red[0] * (1.0f / V_DIM);
    __syncthreads();

    float dx = acc.x - mu, dy = acc.y - mu, dz = acc.z - mu, dw = acc.w - mu;
    red[tid] = dx * dx + dy * dy + dz * dz + dw * dw;
    __syncthreads();
    if (tid < 64) red[tid] += red[tid + 128];
    __syncthreads();
    if (tid < 64) red[tid] += red[tid + 64];
    __syncthreads();
    if (tid < 32) {
        float v = red[tid] + red[tid + 32];
#pragma unroll
        for (int o = 16; o > 0; o >>= 1) v += __shfl_xor_sync(0xffffffffu, v, o);
        if (tid == 0) red[0] = v;
    }
    __syncthreads();
    float var = red[0] * (1.0f / V_DIM);
    float rstd = rsqrtf(var + 1e-12f);

    float4 g4 = ((const float4*)gamma)[tid];
    float4 b4 = ((const float4*)beta)[tid];
    float4 o4;
    o4.x = dx * rstd * g4.x + b4.x;
    o4.y = dy * rstd * g4.y + b4.y;
    o4.z = dz * rstd * g4.z + b4.z;
    o4.w = dw * rstd * g4.w + b4.w;
    ((float4*)(out + (size_t)t * V_DIM))[tid] = o4;
}

// ---------------- launch ---------------------------------------------------
extern "C" void kernel_launch(void* const* d_in, const int* in_sizes, int n_in,
                              void* d_out, int out_size)
{
    const float* hs     = (const float*)d_in[0];
    const float* inp    = (const float*)d_in[1];
    const float* Wd     = (const float*)d_in[2];
    const float* bd     = (const float*)d_in[3];
    const float* Wq     = (const float*)d_in[4];
    const float* bq     = (const float*)d_in[5];
    const float* keys   = (const float*)d_in[6];
    const float* values = (const float*)d_in[7];
    const float* gamma  = (const float*)d_in[8];
    const float* beta   = (const float*)d_in[9];
    float* out = (float*)d_out;

    void* p_C;
    cudaGetSymbolAddress(&p_C, g_C);
    float* C = (float*)p_C;

    cudaFuncSetAttribute(gemm_hmma, cudaFuncAttributeMaxDynamicSharedMemorySize, SMEM_TOTAL);
    cudaFuncSetAttribute(prep_misc, cudaFuncAttributeMaxDynamicSharedMemorySize, PREP_SMEM);

    // order: gemm_hmma is the 4th user kernel (ncu capture slot)
    split_trans<<<49152 + 2304, 256>>>(hs, Wd);
    prep_misc<<<197, 256, PREP_SMEM>>>(Wq, keys, bd, bq);
    cvt_values<<<(N_KEYS * N_KEYS * V_DIM / 4) / 256, 256>>>(values);
    gemm_hmma<<<dim3(NCAT / BN, T_TOT / BM), 128, SMEM_TOTAL>>>(C);
    pkm_fused<<<T_TOT, 192>>>(C, inp, gamma, beta, out);
}